// round 6
// baseline (speedup 1.0000x reference)
#include <cuda_runtime.h>
#include <stdint.h>

// Problem shape (fixed by dataset): N=50000, E=800000, Fin=Fhid=128, Fout=64
#define NMAX 50176
#define EMAX 800000

// -------- static device scratch (no allocations; referenced directly) ------
__device__ int   g_hi_nonzero;               // dtype probe result
__device__ float g_deg[NMAX];
__device__ float g_dinv[NMAX];
__device__ int   g_cnt[NMAX];
__device__ int   g_rowptr[NMAX + 1];
__device__ int   g_cursor[NMAX];
__device__ int   g_esrc[EMAX];
__device__ float g_enrm[EMAX];
__device__ float g_xw[(size_t)NMAX * 128];   // x @ W0
__device__ float g_h[(size_t)NMAX * 128];    // layer-1 activations
__device__ float g_hw[(size_t)NMAX * 64];    // h @ W1

// ----------------------------------------------------------------
// Probe edge_index dtype. Interpreting the buffer as int32:
//  - if true dtype is int64 (LE), odd words are high halves == 0 for all
//    indices < 2^32  -> g_hi_nonzero stays 0
//  - if true dtype is int32, odd words are random row indices -> nonzero
// Reading ei32[2*i+1] for i < min(E,65536) is in-bounds under BOTH dtypes.
__global__ void k_detect(const int* __restrict__ ei32, int E) {
    int i = blockIdx.x * blockDim.x + threadIdx.x;
    int samples = E < 65536 ? E : 65536;
    if (i < samples) {
        if (ei32[2 * i + 1] != 0) atomicOr(&g_hi_nonzero, 1);
    }
}

__global__ void k_init(int N) {
    int i = blockIdx.x * blockDim.x + threadIdx.x;
    if (i < N) { g_deg[i] = 1.0f; g_cnt[i] = 0; }  // self-loop weight 1
    if (i == 0) { /* probe flag reset happens before k_detect */ }
}

__global__ void k_reset_flag() { g_hi_nonzero = 0; }

__device__ __forceinline__ int load_idx(const int* ei32, int pos, int N) {
    // g_hi_nonzero == 0  -> int64 data: low word at 2*pos
    // g_hi_nonzero != 0  -> int32 data: word at pos
    int v = (g_hi_nonzero == 0) ? ei32[2 * pos] : ei32[pos];
    v = v < 0 ? 0 : v;
    return v >= N ? N - 1 : v;
}

// per-edge: weighted degree at target + in-degree histogram
__global__ void k_count(const int* __restrict__ ei32,
                        const float* __restrict__ ew, int E, int N) {
    int e = blockIdx.x * blockDim.x + threadIdx.x;
    if (e >= E) return;
    int c = load_idx(ei32, E + e, N);
    atomicAdd(&g_deg[c], ew[e]);
    atomicAdd(&g_cnt[c], 1);
}

__global__ void k_dinv(int N) {
    int i = blockIdx.x * blockDim.x + threadIdx.x;
    if (i < N) {
        float d = g_deg[i];
        g_dinv[i] = (d > 0.0f) ? rsqrtf(d) : 0.0f;
    }
}

// single-block exclusive scan of g_cnt -> g_rowptr / g_cursor (shared-mem scan)
__global__ void k_scan(int N, int E) {
    __shared__ int sh[1024];
    __shared__ int carry;
    const int tid = threadIdx.x;
    if (tid == 0) carry = 0;
    __syncthreads();
    for (int base = 0; base < N; base += 1024) {
        int i = base + tid;
        int v = (i < N) ? g_cnt[i] : 0;
        sh[tid] = v;
        __syncthreads();
        for (int o = 1; o < 1024; o <<= 1) {
            int t = (tid >= o) ? sh[tid - o] : 0;
            __syncthreads();
            sh[tid] += t;
            __syncthreads();
        }
        int excl = carry + sh[tid] - v;
        if (i < N) { g_rowptr[i] = excl; g_cursor[i] = excl; }
        __syncthreads();
        if (tid == 0) carry += sh[1023];
        __syncthreads();
    }
    if (tid == 0) g_rowptr[N] = E;
}

// per-edge: place (src, norm) into CSR slot of its target
__global__ void k_place(const int* __restrict__ ei32,
                        const float* __restrict__ ew, int E, int N) {
    int e = blockIdx.x * blockDim.x + threadIdx.x;
    if (e >= E) return;
    int r = load_idx(ei32, e, N);
    int c = load_idx(ei32, E + e, N);
    float nrm = g_dinv[r] * ew[e] * g_dinv[c];
    int pos = atomicAdd(&g_cursor[c], 1);
    if (pos >= 0 && pos < EMAX) {
        g_esrc[pos] = r;
        g_enrm[pos] = nrm;
    }
}

// ----------------------------------------------------------------
// SGEMM (all scalar): C[M,N] = A[M,K] @ B[K,N].
// BM=BN=64, BK=16, 256 threads, 4x4 micro-tile per thread.
#define BM 64
#define BN 64
#define BK 16
__global__ __launch_bounds__(256)
void k_sgemm(int layer, const float* __restrict__ Ain,
             const float* __restrict__ B, int M, int N, int K) {
    const float* A = (layer == 0) ? Ain : g_h;
    float*       C = (layer == 0) ? g_xw : g_hw;

    __shared__ float As[BM][BK + 1];
    __shared__ float Bs[BK][BN + 1];
    const int tid = threadIdx.x;
    const int bm = blockIdx.y * BM;
    const int bn = blockIdx.x * BN;
    const int tx = tid & 15;
    const int ty = tid >> 4;

    float acc[4][4];
#pragma unroll
    for (int i = 0; i < 4; i++)
#pragma unroll
        for (int j = 0; j < 4; j++) acc[i][j] = 0.0f;

    for (int k0 = 0; k0 < K; k0 += BK) {
        {
            int r = tid >> 2;
            int c0 = (tid & 3) * 4;
            int m = bm + r;
#pragma unroll
            for (int j = 0; j < 4; j++) {
                float v = 0.0f;
                if (m < M) v = A[(size_t)m * K + k0 + c0 + j];
                As[r][c0 + j] = v;
            }
        }
        {
            int r = tid >> 4;
            int c0 = (tid & 15) * 4;
#pragma unroll
            for (int j = 0; j < 4; j++) {
                Bs[r][c0 + j] = B[(size_t)(k0 + r) * N + bn + c0 + j];
            }
        }
        __syncthreads();

#pragma unroll
        for (int kk = 0; kk < BK; kk++) {
            float a0 = As[ty * 4 + 0][kk];
            float a1 = As[ty * 4 + 1][kk];
            float a2 = As[ty * 4 + 2][kk];
            float a3 = As[ty * 4 + 3][kk];
            float b0 = Bs[kk][tx * 4 + 0];
            float b1 = Bs[kk][tx * 4 + 1];
            float b2 = Bs[kk][tx * 4 + 2];
            float b3 = Bs[kk][tx * 4 + 3];
            acc[0][0] += a0 * b0; acc[0][1] += a0 * b1; acc[0][2] += a0 * b2; acc[0][3] += a0 * b3;
            acc[1][0] += a1 * b0; acc[1][1] += a1 * b1; acc[1][2] += a1 * b2; acc[1][3] += a1 * b3;
            acc[2][0] += a2 * b0; acc[2][1] += a2 * b1; acc[2][2] += a2 * b2; acc[2][3] += a2 * b3;
            acc[3][0] += a3 * b0; acc[3][1] += a3 * b1; acc[3][2] += a3 * b2; acc[3][3] += a3 * b3;
        }
        __syncthreads();
    }

#pragma unroll
    for (int i = 0; i < 4; i++) {
        int m = bm + ty * 4 + i;
        if (m < M) {
#pragma unroll
            for (int j = 0; j < 4; j++) {
                C[(size_t)m * N + bn + tx * 4 + j] = acc[i][j];
            }
        }
    }
}

// ----------------------------------------------------------------
// One warp per destination node: self-loop + CSR gather + bias + ReLU.
// Lane l owns columns {l, l+32, ...}; all loads scalar & coalesced.
template <int F>
__global__ __launch_bounds__(256)
void k_agg(int layer, const float* __restrict__ bias,
           float* __restrict__ outbuf, int N) {
    constexpr int VEC = F / 32;
    const float* src = (layer == 0) ? g_xw : g_hw;
    float*       dst = (layer == 0) ? g_h  : outbuf;

    const int gw = (blockIdx.x * blockDim.x + threadIdx.x) >> 5;
    const int lane = threadIdx.x & 31;
    if (gw >= N) return;

    const int start = g_rowptr[gw];
    const int end   = g_rowptr[gw + 1];

    float acc[VEC];
    {
        float d = g_dinv[gw];
        float sw = d * d;
#pragma unroll
        for (int v = 0; v < VEC; v++)
            acc[v] = sw * src[(size_t)gw * F + v * 32 + lane];
    }

    for (int e = start; e < end; e++) {
        int   s = g_esrc[e];   // uniform across warp -> broadcast load
        float w = g_enrm[e];
        const float* p = src + (size_t)s * F + lane;
#pragma unroll
        for (int v = 0; v < VEC; v++)
            acc[v] += w * p[v * 32];
    }

#pragma unroll
    for (int v = 0; v < VEC; v++) {
        float r = acc[v] + bias[v * 32 + lane];
        dst[(size_t)gw * F + v * 32 + lane] = r > 0.0f ? r : 0.0f;
    }
}

// ----------------------------------------------------------------
extern "C" void kernel_launch(void* const* d_in, const int* in_sizes, int n_in,
                              void* d_out, int out_size) {
    const float* x    = (const float*)d_in[0];
    const int*   ei32 = (const int*)d_in[1];     // raw words; dtype probed on device
    const float* ew   = (const float*)d_in[2];
    const float* W0   = (const float*)d_in[3];
    const float* b0   = (const float*)d_in[4];
    const float* W1   = (const float*)d_in[5];
    const float* b1   = (const float*)d_in[6];
    float* out = (float*)d_out;

    const int Fh  = in_sizes[4];            // 128
    const int Fo  = in_sizes[6];            // 64
    const int Fin = in_sizes[3] / Fh;       // 128
    const int N   = in_sizes[0] / Fin;      // 50000
    const int E   = in_sizes[2];            // 800000

    const int TB = 256;
    // dtype probe + CSR + norm prep
    k_reset_flag<<<1, 1>>>();
    k_detect<<<(65536 + TB - 1) / TB, TB>>>(ei32, E);
    k_init<<<(N + TB - 1) / TB, TB>>>(N);
    k_count<<<(E + TB - 1) / TB, TB>>>(ei32, ew, E, N);
    k_dinv<<<(N + TB - 1) / TB, TB>>>(N);
    k_scan<<<1, 1024>>>(N, E);
    k_place<<<(E + TB - 1) / TB, TB>>>(ei32, ew, E, N);

    // layer 1: g_xw = x @ W0 ; g_h = agg(g_xw) + b0, ReLU
    {
        dim3 grid(Fh / BN, (N + BM - 1) / BM);
        k_sgemm<<<grid, 256>>>(0, x, W0, N, Fh, Fin);
    }
    k_agg<128><<<(N * 32 + TB - 1) / TB, TB>>>(0, b0, out, N);

    // layer 2: g_hw = g_h @ W1 ; out = agg(g_hw) + b1, ReLU
    {
        dim3 grid(Fo / BN, (N + BM - 1) / BM);
        k_sgemm<<<grid, 256>>>(1, nullptr, W1, N, Fo, Fh);
    }
    k_agg<64><<<(N * 32 + TB - 1) / TB, TB>>>(1, b1, out, N);
}

// round 7
// speedup vs baseline: 1.3502x; 1.3502x over previous
#include <cuda_runtime.h>
#include <stdint.h>

// Problem shape (fixed by dataset): N=50000, E=800000, Fin=Fhid=128, Fout=64
#define NMAX 50176
#define EMAX 800000

// -------- static device scratch (no allocations; referenced directly) ------
__device__ int   g_hi_nonzero;               // dtype probe result
__device__ float g_deg[NMAX];
__device__ float g_dinv[NMAX];
__device__ int   g_cnt[NMAX];
__device__ int   g_rowptr[NMAX + 1];
__device__ int   g_cursor[NMAX];
__device__ int   g_bsum[64];
__device__ int   g_boff[64];
__device__ int   g_esrc[EMAX];
__device__ float g_enrm[EMAX];
__device__ float g_xw[(size_t)NMAX * 128];   // x @ W0
__device__ float g_h[(size_t)NMAX * 128];    // layer-1 activations
__device__ float g_hw[(size_t)NMAX * 64];    // h @ W1

// ---------------- packed f32x2 helpers (Blackwell) ----------------
__device__ __forceinline__ unsigned long long pack2(float x) {
    unsigned long long r;
    asm("mov.b64 %0, {%1, %1};" : "=l"(r) : "f"(x));
    return r;
}
__device__ __forceinline__ void fma2(unsigned long long& d,
                                     unsigned long long a,
                                     unsigned long long b) {
    asm("fma.rn.f32x2 %0, %1, %2, %3;" : "=l"(d) : "l"(a), "l"(b), "l"(d));
}
__device__ __forceinline__ float2 unpack2(unsigned long long v) {
    float lo, hi;
    asm("mov.b64 {%0, %1}, %2;" : "=f"(lo), "=f"(hi) : "l"(v));
    return make_float2(lo, hi);
}

// ----------------------------------------------------------------
// Probe edge_index dtype (int64 vs int32); see round-6 notes.
__global__ void k_detect(const int* __restrict__ ei32, int E) {
    int i = blockIdx.x * blockDim.x + threadIdx.x;
    int samples = E < 65536 ? E : 65536;
    if (i < samples) {
        if (ei32[2 * i + 1] != 0) atomicOr(&g_hi_nonzero, 1);
    }
}

__global__ void k_init(int N) {
    int i = blockIdx.x * blockDim.x + threadIdx.x;
    if (i < N) { g_deg[i] = 1.0f; g_cnt[i] = 0; }  // self-loop weight 1
}

__global__ void k_reset_flag() { g_hi_nonzero = 0; }

__device__ __forceinline__ int load_idx(const int* ei32, int pos, int N) {
    int v = (g_hi_nonzero == 0) ? ei32[2 * pos] : ei32[pos];
    v = v < 0 ? 0 : v;
    return v >= N ? N - 1 : v;
}

// per-edge: weighted degree at target + in-degree histogram
__global__ void k_count(const int* __restrict__ ei32,
                        const float* __restrict__ ew, int E, int N) {
    int e = blockIdx.x * blockDim.x + threadIdx.x;
    if (e >= E) return;
    int c = load_idx(ei32, E + e, N);
    atomicAdd(&g_deg[c], ew[e]);
    atomicAdd(&g_cnt[c], 1);
}

__global__ void k_dinv(int N) {
    int i = blockIdx.x * blockDim.x + threadIdx.x;
    if (i < N) {
        float d = g_deg[i];
        g_dinv[i] = (d > 0.0f) ? rsqrtf(d) : 0.0f;
    }
}

// ---- parallel 3-stage exclusive scan of g_cnt -> g_rowptr / g_cursor ----
__global__ void k_scan1(int N) {   // block-local scan, 1024 thr/block
    __shared__ int sh[1024];
    const int t = threadIdx.x;
    const int i = blockIdx.x * 1024 + t;
    int v = (i < N) ? g_cnt[i] : 0;
    sh[t] = v;
    __syncthreads();
    for (int o = 1; o < 1024; o <<= 1) {
        int u = (t >= o) ? sh[t - o] : 0;
        __syncthreads();
        sh[t] += u;
        __syncthreads();
    }
    if (i < N) g_rowptr[i] = sh[t] - v;     // local exclusive
    if (t == 1023) g_bsum[blockIdx.x] = sh[1023];
}
__global__ void k_scan2(int nb) {  // scan of block sums (nb <= 64)
    __shared__ int sh[64];
    const int t = threadIdx.x;
    int v = (t < nb) ? g_bsum[t] : 0;
    sh[t] = v;
    __syncthreads();
    for (int o = 1; o < 64; o <<= 1) {
        int u = (t >= o) ? sh[t - o] : 0;
        __syncthreads();
        sh[t] += u;
        __syncthreads();
    }
    if (t < nb) g_boff[t] = sh[t] - v;      // exclusive
}
__global__ void k_scan3(int N, int E) {     // add offsets, init cursor
    const int i = blockIdx.x * 1024 + threadIdx.x;
    if (i < N) {
        int r = g_rowptr[i] + g_boff[i >> 10];
        g_rowptr[i] = r;
        g_cursor[i] = r;
    }
    if (i == 0) g_rowptr[N] = E;
}

// per-edge: place (src, norm) into CSR slot of its target
__global__ void k_place(const int* __restrict__ ei32,
                        const float* __restrict__ ew, int E, int N) {
    int e = blockIdx.x * blockDim.x + threadIdx.x;
    if (e >= E) return;
    int r = load_idx(ei32, e, N);
    int c = load_idx(ei32, E + e, N);
    float nrm = g_dinv[r] * ew[e] * g_dinv[c];
    int pos = atomicAdd(&g_cursor[c], 1);
    if (pos >= 0 && pos < EMAX) {
        g_esrc[pos] = r;
        g_enrm[pos] = nrm;
    }
}

// ----------------------------------------------------------------
// Packed-f32x2 SGEMM: C[M,BN_] = A[M,K] @ B[K,BN_].
// BM=128, BK=16, 256 threads. TN=8 cols/thread; TM_ rows/thread.
// BN_=128 -> TM_=8 (layer 1), BN_=64 -> TM_=4 (layer 2).
// layer==0: A=Ain (x), C=g_xw.  layer==1: A=g_h, C=g_hw.
template <int BN_, int TM_>
__global__ __launch_bounds__(256)
void k_sgemm2(int layer, const float* __restrict__ Ain, const float* __restrict__ B,
              int M, int K) {
    constexpr int BM = 128, BK = 16, TN = 8;
    constexpr int NCOL = BN_ / TN;            // threads along N
    const float* A = (layer == 0) ? Ain : g_h;
    float*       C = (layer == 0) ? g_xw : g_hw;

    __shared__ float As[BM][BK];
    __shared__ float Bs[BK][BN_];

    const int tid = threadIdx.x;
    const int bm  = blockIdx.x * BM;
    const int tx  = tid % NCOL;
    const int ty  = tid / NCOL;

    unsigned long long acc[TM_][TN / 2];
#pragma unroll
    for (int i = 0; i < TM_; i++)
#pragma unroll
        for (int j = 0; j < TN / 2; j++) acc[i][j] = 0ull;

    for (int k0 = 0; k0 < K; k0 += BK) {
        // A tile 128x16: thread loads 2 float4 of row m = tid>>1
        {
            int m  = tid >> 1;
            int kc = (tid & 1) * 8;
            int gm = bm + m;
            float4 v0 = make_float4(0.f, 0.f, 0.f, 0.f);
            float4 v1 = v0;
            if (gm < M) {
                const float* p = A + (size_t)gm * K + k0 + kc;
                v0 = *(const float4*)(p);
                v1 = *(const float4*)(p + 4);
            }
            *(float4*)&As[m][kc]     = v0;
            *(float4*)&As[m][kc + 4] = v1;
        }
        // B tile 16xBN_: (BK*BN_/4) float4s over 256 threads
        {
            constexpr int NF4 = BK * BN_ / 4;
#pragma unroll
            for (int i = 0; i < NF4 / 256; i++) {
                int idx4 = i * 256 + tid;
                int r  = idx4 / (BN_ / 4);
                int c4 = idx4 % (BN_ / 4);
                *(float4*)&Bs[r][c4 * 4] =
                    *(const float4*)&B[(size_t)(k0 + r) * BN_ + c4 * 4];
            }
        }
        __syncthreads();

#pragma unroll
        for (int kk = 0; kk < BK; kk++) {
            unsigned long long b2[TN / 2];
            const unsigned long long* bp =
                (const unsigned long long*)&Bs[kk][tx * TN];
#pragma unroll
            for (int j = 0; j < TN / 2; j++) b2[j] = bp[j];
#pragma unroll
            for (int i = 0; i < TM_; i++) {
                unsigned long long a2 = pack2(As[ty * TM_ + i][kk]);
#pragma unroll
                for (int j = 0; j < TN / 2; j++) fma2(acc[i][j], a2, b2[j]);
            }
        }
        __syncthreads();
    }

#pragma unroll
    for (int i = 0; i < TM_; i++) {
        int m = bm + ty * TM_ + i;
        if (m < M) {
            float2* cp = (float2*)&C[(size_t)m * BN_ + tx * TN];
#pragma unroll
            for (int j = 0; j < TN / 2; j++) cp[j] = unpack2(acc[i][j]);
        }
    }
}

// ----------------------------------------------------------------
// One warp per destination node: self-loop + CSR gather + bias + ReLU.
// F=128: lane owns float4 at cols [4l,4l+4). F=64: float2 at [2l,2l+2).
template <int F>
__global__ __launch_bounds__(256)
void k_agg(int layer, const float* __restrict__ bias,
           float* __restrict__ outbuf, int N) {
    const float* src = (layer == 0) ? g_xw : g_hw;
    float*       dst = (layer == 0) ? g_h  : outbuf;

    const int gw   = (blockIdx.x * blockDim.x + threadIdx.x) >> 5;
    const int lane = threadIdx.x & 31;
    if (gw >= N) return;

    const int start = g_rowptr[gw];
    const int end   = g_rowptr[gw + 1];

    if constexpr (F == 128) {
        float4 acc;
        {
            float d = g_dinv[gw];
            float sw = d * d;
            float4 v = ((const float4*)(src + (size_t)gw * F))[lane];
            acc = make_float4(sw * v.x, sw * v.y, sw * v.z, sw * v.w);
        }
        int e = start;
        for (; e + 4 <= end; e += 4) {
            int   s0 = g_esrc[e],     s1 = g_esrc[e + 1];
            int   s2 = g_esrc[e + 2], s3 = g_esrc[e + 3];
            float w0 = g_enrm[e],     w1 = g_enrm[e + 1];
            float w2 = g_enrm[e + 2], w3 = g_enrm[e + 3];
            float4 v0 = ((const float4*)(src + (size_t)s0 * F))[lane];
            float4 v1 = ((const float4*)(src + (size_t)s1 * F))[lane];
            float4 v2 = ((const float4*)(src + (size_t)s2 * F))[lane];
            float4 v3 = ((const float4*)(src + (size_t)s3 * F))[lane];
            acc.x += w0 * v0.x + w1 * v1.x + w2 * v2.x + w3 * v3.x;
            acc.y += w0 * v0.y + w1 * v1.y + w2 * v2.y + w3 * v3.y;
            acc.z += w0 * v0.z + w1 * v1.z + w2 * v2.z + w3 * v3.z;
            acc.w += w0 * v0.w + w1 * v1.w + w2 * v2.w + w3 * v3.w;
        }
        for (; e < end; e++) {
            int   s = g_esrc[e];
            float w = g_enrm[e];
            float4 v = ((const float4*)(src + (size_t)s * F))[lane];
            acc.x += w * v.x; acc.y += w * v.y;
            acc.z += w * v.z; acc.w += w * v.w;
        }
        float4 bv = ((const float4*)bias)[lane];
        acc.x = fmaxf(acc.x + bv.x, 0.f);
        acc.y = fmaxf(acc.y + bv.y, 0.f);
        acc.z = fmaxf(acc.z + bv.z, 0.f);
        acc.w = fmaxf(acc.w + bv.w, 0.f);
        ((float4*)(dst + (size_t)gw * F))[lane] = acc;
    } else {
        float2 acc;
        {
            float d = g_dinv[gw];
            float sw = d * d;
            float2 v = ((const float2*)(src + (size_t)gw * F))[lane];
            acc = make_float2(sw * v.x, sw * v.y);
        }
        int e = start;
        for (; e + 4 <= end; e += 4) {
            int   s0 = g_esrc[e],     s1 = g_esrc[e + 1];
            int   s2 = g_esrc[e + 2], s3 = g_esrc[e + 3];
            float w0 = g_enrm[e],     w1 = g_enrm[e + 1];
            float w2 = g_enrm[e + 2], w3 = g_enrm[e + 3];
            float2 v0 = ((const float2*)(src + (size_t)s0 * F))[lane];
            float2 v1 = ((const float2*)(src + (size_t)s1 * F))[lane];
            float2 v2 = ((const float2*)(src + (size_t)s2 * F))[lane];
            float2 v3 = ((const float2*)(src + (size_t)s3 * F))[lane];
            acc.x += w0 * v0.x + w1 * v1.x + w2 * v2.x + w3 * v3.x;
            acc.y += w0 * v0.y + w1 * v1.y + w2 * v2.y + w3 * v3.y;
        }
        for (; e < end; e++) {
            int   s = g_esrc[e];
            float w = g_enrm[e];
            float2 v = ((const float2*)(src + (size_t)s * F))[lane];
            acc.x += w * v.x; acc.y += w * v.y;
        }
        float2 bv = ((const float2*)bias)[lane];
        acc.x = fmaxf(acc.x + bv.x, 0.f);
        acc.y = fmaxf(acc.y + bv.y, 0.f);
        ((float2*)(dst + (size_t)gw * F))[lane] = acc;
    }
}

// ----------------------------------------------------------------
extern "C" void kernel_launch(void* const* d_in, const int* in_sizes, int n_in,
                              void* d_out, int out_size) {
    const float* x    = (const float*)d_in[0];
    const int*   ei32 = (const int*)d_in[1];     // raw words; dtype probed on device
    const float* ew   = (const float*)d_in[2];
    const float* W0   = (const float*)d_in[3];
    const float* b0   = (const float*)d_in[4];
    const float* W1   = (const float*)d_in[5];
    const float* b1   = (const float*)d_in[6];
    float* out = (float*)d_out;

    const int Fh  = in_sizes[4];            // 128
    const int Fo  = in_sizes[6];            // 64
    const int Fin = in_sizes[3] / Fh;       // 128
    const int N   = in_sizes[0] / Fin;      // 50000
    const int E   = in_sizes[2];            // 800000

    const int TB = 256;
    const int nScanBlocks = (N + 1023) / 1024;

    // dtype probe + CSR + norm prep
    k_reset_flag<<<1, 1>>>();
    k_detect<<<(65536 + TB - 1) / TB, TB>>>(ei32, E);
    k_init<<<(N + TB - 1) / TB, TB>>>(N);
    k_count<<<(E + TB - 1) / TB, TB>>>(ei32, ew, E, N);
    k_dinv<<<(N + TB - 1) / TB, TB>>>(N);
    k_scan1<<<nScanBlocks, 1024>>>(N);
    k_scan2<<<1, 64>>>(nScanBlocks);
    k_scan3<<<nScanBlocks, 1024>>>(N, E);
    k_place<<<(E + TB - 1) / TB, TB>>>(ei32, ew, E, N);

    // layer 1: g_xw = x @ W0 ; g_h = agg(g_xw) + b0, ReLU
    k_sgemm2<128, 8><<<(N + 127) / 128, 256>>>(0, x, W0, N, Fin);
    k_agg<128><<<(N * 32 + TB - 1) / TB, TB>>>(0, b0, out, N);

    // layer 2: g_hw = g_h @ W1 ; out = agg(g_hw) + b1, ReLU
    k_sgemm2<64, 4><<<(N + 127) / 128, 256>>>(1, nullptr, W1, N, Fh);
    k_agg<64><<<(N * 32 + TB - 1) / TB, TB>>>(1, b1, out, N);
}

// round 8
// speedup vs baseline: 1.4643x; 1.0845x over previous
#include <cuda_runtime.h>
#include <stdint.h>

// Problem shape (fixed by dataset): N=50000, E=800000, Fin=Fhid=128, Fout=64
#define NMAX 50176
#define EMAX 800000

// -------- static device scratch (no allocations; referenced directly) ------
__device__ int   g_hi_nonzero;               // dtype probe result
__device__ float g_dinv[NMAX];
__device__ int   g_cnt[NMAX];
__device__ int   g_rowptr[NMAX + 1];
__device__ int   g_cursor[NMAX];
__device__ int   g_bsum[64];
__device__ int   g_boff[64];
__device__ int2  g_emeta[EMAX];              // {src, ew-as-int-bits}
__device__ float g_xw[(size_t)NMAX * 128];   // x @ W0
__device__ float g_h[(size_t)NMAX * 128];    // layer-1 activations
__device__ float g_hw[(size_t)NMAX * 64];    // h @ W1

// ---------------- packed f32x2 helpers (Blackwell) ----------------
__device__ __forceinline__ unsigned long long pack2(float x) {
    unsigned long long r;
    asm("mov.b64 %0, {%1, %1};" : "=l"(r) : "f"(x));
    return r;
}
__device__ __forceinline__ void fma2(unsigned long long& d,
                                     unsigned long long a,
                                     unsigned long long b) {
    asm("fma.rn.f32x2 %0, %1, %2, %3;" : "=l"(d) : "l"(a), "l"(b), "l"(d));
}
__device__ __forceinline__ float2 unpack2(unsigned long long v) {
    float lo, hi;
    asm("mov.b64 {%0, %1}, %2;" : "=f"(lo), "=f"(hi) : "l"(v));
    return make_float2(lo, hi);
}

// ----------------------------------------------------------------
// Probe edge_index dtype (int64 vs int32): as int32 words, int64 data has
// all odd words == 0 (high halves); int32 data has random indices there.
__global__ void k_detect(const int* __restrict__ ei32, int E) {
    int i = blockIdx.x * blockDim.x + threadIdx.x;
    int samples = E < 65536 ? E : 65536;
    if (i < samples) {
        if (ei32[2 * i + 1] != 0) atomicOr(&g_hi_nonzero, 1);
    }
}

__global__ void k_init(int N) {
    int i = blockIdx.x * blockDim.x + threadIdx.x;
    if (i < N) g_cnt[i] = 0;
}

__global__ void k_reset_flag() { g_hi_nonzero = 0; }

__device__ __forceinline__ int load_idx(const int* ei32, int pos, int N) {
    int v = (g_hi_nonzero == 0) ? ei32[2 * pos] : ei32[pos];
    v = v < 0 ? 0 : v;
    return v >= N ? N - 1 : v;
}

// per-edge: in-degree histogram (single int atomic)
__global__ void k_count(const int* __restrict__ ei32, int E, int N) {
    int e = blockIdx.x * blockDim.x + threadIdx.x;
    if (e >= E) return;
    int c = load_idx(ei32, E + e, N);
    atomicAdd(&g_cnt[c], 1);
}

// ---- parallel 3-stage exclusive scan of g_cnt -> g_rowptr / g_cursor ----
__global__ void k_scan1(int N) {
    __shared__ int sh[1024];
    const int t = threadIdx.x;
    const int i = blockIdx.x * 1024 + t;
    int v = (i < N) ? g_cnt[i] : 0;
    sh[t] = v;
    __syncthreads();
    for (int o = 1; o < 1024; o <<= 1) {
        int u = (t >= o) ? sh[t - o] : 0;
        __syncthreads();
        sh[t] += u;
        __syncthreads();
    }
    if (i < N) g_rowptr[i] = sh[t] - v;     // local exclusive
    if (t == 1023) g_bsum[blockIdx.x] = sh[1023];
}
__global__ void k_scan2(int nb) {
    __shared__ int sh[64];
    const int t = threadIdx.x;
    int v = (t < nb) ? g_bsum[t] : 0;
    sh[t] = v;
    __syncthreads();
    for (int o = 1; o < 64; o <<= 1) {
        int u = (t >= o) ? sh[t - o] : 0;
        __syncthreads();
        sh[t] += u;
        __syncthreads();
    }
    if (t < nb) g_boff[t] = sh[t] - v;      // exclusive
}
__global__ void k_scan3(int N, int E) {
    const int i = blockIdx.x * 1024 + threadIdx.x;
    if (i < N) {
        int r = g_rowptr[i] + g_boff[i >> 10];
        g_rowptr[i] = r;
        g_cursor[i] = r;
    }
    if (i == 0) g_rowptr[N] = E;
}

// per-edge: place {src, ew} into CSR slot of its target
__global__ void k_place(const int* __restrict__ ei32,
                        const float* __restrict__ ew, int E, int N) {
    int e = blockIdx.x * blockDim.x + threadIdx.x;
    if (e >= E) return;
    int r = load_idx(ei32, e, N);
    int c = load_idx(ei32, E + e, N);
    int pos = atomicAdd(&g_cursor[c], 1);
    if (pos >= 0 && pos < EMAX) {
        g_emeta[pos] = make_int2(r, __float_as_int(ew[e]));
    }
}

// per-node: weighted degree (self-loop 1 + segment ew sum) -> dinv
__global__ void k_deg(int N) {
    int i = blockIdx.x * blockDim.x + threadIdx.x;
    if (i >= N) return;
    int s = g_rowptr[i], e = g_rowptr[i + 1];
    float d = 1.0f;
    for (int p = s; p < e; p++) d += __int_as_float(g_emeta[p].y);
    g_dinv[i] = rsqrtf(d);
}

// ----------------------------------------------------------------
// Packed-f32x2 SGEMM: C[M,BN_] = A[M,K] @ B[K,BN_].
// BM=128, BK=16, 256 threads; TN=8 cols/thread; TM_ rows/thread.
// As stored k-major so per-kk A reads are 2 (or 1) LDS.128.
template <int BN_, int TM_>
__global__ __launch_bounds__(256)
void k_sgemm2(int layer, const float* __restrict__ Ain, const float* __restrict__ B,
              int M, int K) {
    constexpr int BM = 128, BK = 16, TN = 8;
    constexpr int NCOL = BN_ / TN;            // threads along N
    const float* A = (layer == 0) ? Ain : g_h;
    float*       C = (layer == 0) ? g_xw : g_hw;

    __shared__ float As[BK][BM];              // k-major
    __shared__ float Bs[BK][BN_];

    const int tid = threadIdx.x;
    const int bm  = blockIdx.x * BM;
    const int tx  = tid % NCOL;
    const int ty  = tid / NCOL;

    unsigned long long acc[TM_][TN / 2];
#pragma unroll
    for (int i = 0; i < TM_; i++)
#pragma unroll
        for (int j = 0; j < TN / 2; j++) acc[i][j] = 0ull;

    for (int k0 = 0; k0 < K; k0 += BK) {
        // A tile 128x16 -> transposed into As[k][m]
        {
            int m  = tid >> 1;
            int kc = (tid & 1) * 8;
            int gm = bm + m;
            float4 v0 = make_float4(0.f, 0.f, 0.f, 0.f);
            float4 v1 = v0;
            if (gm < M) {
                const float* p = A + (size_t)gm * K + k0 + kc;
                v0 = *(const float4*)(p);
                v1 = *(const float4*)(p + 4);
            }
            As[kc + 0][m] = v0.x; As[kc + 1][m] = v0.y;
            As[kc + 2][m] = v0.z; As[kc + 3][m] = v0.w;
            As[kc + 4][m] = v1.x; As[kc + 5][m] = v1.y;
            As[kc + 6][m] = v1.z; As[kc + 7][m] = v1.w;
        }
        // B tile 16xBN_
        {
            constexpr int NF4 = BK * BN_ / 4;
#pragma unroll
            for (int i = 0; i < NF4 / 256; i++) {
                int idx4 = i * 256 + tid;
                int r  = idx4 / (BN_ / 4);
                int c4 = idx4 % (BN_ / 4);
                *(float4*)&Bs[r][c4 * 4] =
                    *(const float4*)&B[(size_t)(k0 + r) * BN_ + c4 * 4];
            }
        }
        __syncthreads();

#pragma unroll
        for (int kk = 0; kk < BK; kk++) {
            float av[TM_];
            {
                const float4* ap = (const float4*)&As[kk][ty * TM_];
                float4 a0 = ap[0];
                av[0] = a0.x; av[1] = a0.y; av[2] = a0.z; av[3] = a0.w;
                if constexpr (TM_ == 8) {
                    float4 a1 = ap[1];
                    av[4] = a1.x; av[5] = a1.y; av[6] = a1.z; av[7] = a1.w;
                }
            }
            unsigned long long b2[TN / 2];
            {
                const unsigned long long* bp =
                    (const unsigned long long*)&Bs[kk][tx * TN];
#pragma unroll
                for (int j = 0; j < TN / 2; j++) b2[j] = bp[j];
            }
#pragma unroll
            for (int i = 0; i < TM_; i++) {
                unsigned long long a2 = pack2(av[i]);
#pragma unroll
                for (int j = 0; j < TN / 2; j++) fma2(acc[i][j], a2, b2[j]);
            }
        }
        __syncthreads();
    }

#pragma unroll
    for (int i = 0; i < TM_; i++) {
        int m = bm + ty * TM_ + i;
        if (m < M) {
            float2* cp = (float2*)&C[(size_t)m * BN_ + tx * TN];
#pragma unroll
            for (int j = 0; j < TN / 2; j++) cp[j] = unpack2(acc[i][j]);
        }
    }
}

// ----------------------------------------------------------------
// One warp per destination node: self-loop + CSR gather + bias + ReLU.
// out = dinv_c * [ dinv_c*x_c + sum_e ew_e*dinv[s_e]*x_{s_e} ] + bias, ReLU.
template <int F>
__global__ __launch_bounds__(256)
void k_agg(int layer, const float* __restrict__ bias,
           float* __restrict__ outbuf, int N) {
    const float* src = (layer == 0) ? g_xw : g_hw;
    float*       dst = (layer == 0) ? g_h  : outbuf;

    const int gw   = (blockIdx.x * blockDim.x + threadIdx.x) >> 5;
    const int lane = threadIdx.x & 31;
    if (gw >= N) return;

    const int start = g_rowptr[gw];
    const int end   = g_rowptr[gw + 1];
    const float dc  = g_dinv[gw];

    if constexpr (F == 128) {
        float4 acc;
        {
            float4 v = ((const float4*)(src + (size_t)gw * F))[lane];
            acc = make_float4(dc * v.x, dc * v.y, dc * v.z, dc * v.w);
        }
        int e = start;
        for (; e + 4 <= end; e += 4) {
            int2 m0 = g_emeta[e],     m1 = g_emeta[e + 1];
            int2 m2 = g_emeta[e + 2], m3 = g_emeta[e + 3];
            float w0 = __int_as_float(m0.y) * g_dinv[m0.x];
            float w1 = __int_as_float(m1.y) * g_dinv[m1.x];
            float w2 = __int_as_float(m2.y) * g_dinv[m2.x];
            float w3 = __int_as_float(m3.y) * g_dinv[m3.x];
            float4 v0 = ((const float4*)(src + (size_t)m0.x * F))[lane];
            float4 v1 = ((const float4*)(src + (size_t)m1.x * F))[lane];
            float4 v2 = ((const float4*)(src + (size_t)m2.x * F))[lane];
            float4 v3 = ((const float4*)(src + (size_t)m3.x * F))[lane];
            acc.x += w0 * v0.x + w1 * v1.x + w2 * v2.x + w3 * v3.x;
            acc.y += w0 * v0.y + w1 * v1.y + w2 * v2.y + w3 * v3.y;
            acc.z += w0 * v0.z + w1 * v1.z + w2 * v2.z + w3 * v3.z;
            acc.w += w0 * v0.w + w1 * v1.w + w2 * v2.w + w3 * v3.w;
        }
        for (; e < end; e++) {
            int2 m = g_emeta[e];
            float w = __int_as_float(m.y) * g_dinv[m.x];
            float4 v = ((const float4*)(src + (size_t)m.x * F))[lane];
            acc.x += w * v.x; acc.y += w * v.y;
            acc.z += w * v.z; acc.w += w * v.w;
        }
        float4 bv = ((const float4*)bias)[lane];
        acc.x = fmaxf(dc * acc.x + bv.x, 0.f);
        acc.y = fmaxf(dc * acc.y + bv.y, 0.f);
        acc.z = fmaxf(dc * acc.z + bv.z, 0.f);
        acc.w = fmaxf(dc * acc.w + bv.w, 0.f);
        ((float4*)(dst + (size_t)gw * F))[lane] = acc;
    } else {
        float2 acc;
        {
            float2 v = ((const float2*)(src + (size_t)gw * F))[lane];
            acc = make_float2(dc * v.x, dc * v.y);
        }
        int e = start;
        for (; e + 4 <= end; e += 4) {
            int2 m0 = g_emeta[e],     m1 = g_emeta[e + 1];
            int2 m2 = g_emeta[e + 2], m3 = g_emeta[e + 3];
            float w0 = __int_as_float(m0.y) * g_dinv[m0.x];
            float w1 = __int_as_float(m1.y) * g_dinv[m1.x];
            float w2 = __int_as_float(m2.y) * g_dinv[m2.x];
            float w3 = __int_as_float(m3.y) * g_dinv[m3.x];
            float2 v0 = ((const float2*)(src + (size_t)m0.x * F))[lane];
            float2 v1 = ((const float2*)(src + (size_t)m1.x * F))[lane];
            float2 v2 = ((const float2*)(src + (size_t)m2.x * F))[lane];
            float2 v3 = ((const float2*)(src + (size_t)m3.x * F))[lane];
            acc.x += w0 * v0.x + w1 * v1.x + w2 * v2.x + w3 * v3.x;
            acc.y += w0 * v0.y + w1 * v1.y + w2 * v2.y + w3 * v3.y;
        }
        for (; e < end; e++) {
            int2 m = g_emeta[e];
            float w = __int_as_float(m.y) * g_dinv[m.x];
            float2 v = ((const float2*)(src + (size_t)m.x * F))[lane];
            acc.x += w * v.x; acc.y += w * v.y;
        }
        float2 bv = ((const float2*)bias)[lane];
        acc.x = fmaxf(dc * acc.x + bv.x, 0.f);
        acc.y = fmaxf(dc * acc.y + bv.y, 0.f);
        ((float2*)(dst + (size_t)gw * F))[lane] = acc;
    }
}

// ----------------------------------------------------------------
extern "C" void kernel_launch(void* const* d_in, const int* in_sizes, int n_in,
                              void* d_out, int out_size) {
    const float* x    = (const float*)d_in[0];
    const int*   ei32 = (const int*)d_in[1];     // raw words; dtype probed on device
    const float* ew   = (const float*)d_in[2];
    const float* W0   = (const float*)d_in[3];
    const float* b0   = (const float*)d_in[4];
    const float* W1   = (const float*)d_in[5];
    const float* b1   = (const float*)d_in[6];
    float* out = (float*)d_out;

    const int Fh  = in_sizes[4];            // 128
    const int Fo  = in_sizes[6];            // 64
    const int Fin = in_sizes[3] / Fh;       // 128
    const int N   = in_sizes[0] / Fin;      // 50000
    const int E   = in_sizes[2];            // 800000

    const int TB = 256;
    const int nScanBlocks = (N + 1023) / 1024;

    // dtype probe + CSR prep
    k_reset_flag<<<1, 1>>>();
    k_detect<<<(65536 + TB - 1) / TB, TB>>>(ei32, E);
    k_init<<<(N + TB - 1) / TB, TB>>>(N);
    k_count<<<(E + TB - 1) / TB, TB>>>(ei32, E, N);
    k_scan1<<<nScanBlocks, 1024>>>(N);
    k_scan2<<<1, 64>>>(nScanBlocks);
    k_scan3<<<nScanBlocks, 1024>>>(N, E);
    k_place<<<(E + TB - 1) / TB, TB>>>(ei32, ew, E, N);
    k_deg<<<(N + TB - 1) / TB, TB>>>(N);

    // layer 1: g_xw = x @ W0 ; g_h = agg(g_xw) + b0, ReLU
    k_sgemm2<128, 8><<<(N + 127) / 128, 256>>>(0, x, W0, N, Fin);
    k_agg<128><<<(N * 32 + TB - 1) / TB, TB>>>(0, b0, out, N);

    // layer 2: g_hw = g_h @ W1 ; out = agg(g_hw) + b1, ReLU
    k_sgemm2<64, 4><<<(N + 127) / 128, 256>>>(1, nullptr, W1, N, Fh);
    k_agg<64><<<(N * 32 + TB - 1) / TB, TB>>>(1, b1, out, N);
}

// round 10
// speedup vs baseline: 1.6027x; 1.0945x over previous
#include <cuda_runtime.h>
#include <cuda_fp16.h>
#include <stdint.h>

// Problem shape (fixed by dataset): N=50000, E=800000, Fin=Fhid=128, Fout=64
#define NMAX 50176
#define EMAX 800000

// -------- static device scratch (no allocations; referenced directly) ------
__device__ int    g_hi_nonzero;               // dtype probe result
__device__ float  g_dinv[NMAX];
__device__ int    g_cnt[NMAX];
__device__ int    g_rowptr[NMAX + 1];
__device__ int    g_cursor[NMAX];
__device__ int    g_bsum[64];
__device__ int    g_boff[64];
__device__ int2   g_emeta[EMAX];              // {src, ew-as-int-bits}
__device__ __half g_xwh[(size_t)NMAX * 128];  // x @ W0   (fp16 gather source)
__device__ float  g_h[(size_t)NMAX * 128];    // layer-1 activations (fp32)
__device__ __half g_hwh[(size_t)NMAX * 64];   // h @ W1   (fp16 gather source)

// ---------------- packed f32x2 helpers (Blackwell) ----------------
__device__ __forceinline__ unsigned long long pack2(float x) {
    unsigned long long r;
    asm("mov.b64 %0, {%1, %1};" : "=l"(r) : "f"(x));
    return r;
}
__device__ __forceinline__ void fma2(unsigned long long& d,
                                     unsigned long long a,
                                     unsigned long long b) {
    asm("fma.rn.f32x2 %0, %1, %2, %3;" : "=l"(d) : "l"(a), "l"(b), "l"(d));
}
__device__ __forceinline__ float2 unpack2(unsigned long long v) {
    float lo, hi;
    asm("mov.b64 {%0, %1}, %2;" : "=f"(lo), "=f"(hi) : "l"(v));
    return make_float2(lo, hi);
}

// ----------------------------------------------------------------
// Probe edge_index dtype (int64 vs int32): as int32 words, int64 data has
// all odd words == 0 (high halves); int32 data has random indices there.
__global__ void k_detect(const int* __restrict__ ei32, int E) {
    int i = blockIdx.x * blockDim.x + threadIdx.x;
    int samples = E < 65536 ? E : 65536;
    if (i < samples) {
        if (ei32[2 * i + 1] != 0) atomicOr(&g_hi_nonzero, 1);
    }
}

__global__ void k_init(int N) {
    int i = blockIdx.x * blockDim.x + threadIdx.x;
    if (i < N) g_cnt[i] = 0;
}

__global__ void k_reset_flag() { g_hi_nonzero = 0; }

__device__ __forceinline__ int load_idx(const int* ei32, int pos, int N) {
    int v = (g_hi_nonzero == 0) ? ei32[2 * pos] : ei32[pos];
    v = v < 0 ? 0 : v;
    return v >= N ? N - 1 : v;
}

// per-edge: in-degree histogram; 4 edges/thread for MLP
__global__ void k_count(const int* __restrict__ ei32, int E, int N) {
    int base = (blockIdx.x * blockDim.x + threadIdx.x) * 4;
    int c[4];
    int n = 0;
#pragma unroll
    for (int j = 0; j < 4; j++) {
        int e = base + j;
        if (e < E) { c[n++] = load_idx(ei32, E + e, N); }
    }
#pragma unroll
    for (int j = 0; j < 4; j++) {
        if (j < n) atomicAdd(&g_cnt[c[j]], 1);
    }
}

// ---- parallel 3-stage exclusive scan of g_cnt -> g_rowptr / g_cursor ----
__global__ void k_scan1(int N) {
    __shared__ int sh[1024];
    const int t = threadIdx.x;
    const int i = blockIdx.x * 1024 + t;
    int v = (i < N) ? g_cnt[i] : 0;
    sh[t] = v;
    __syncthreads();
    for (int o = 1; o < 1024; o <<= 1) {
        int u = (t >= o) ? sh[t - o] : 0;
        __syncthreads();
        sh[t] += u;
        __syncthreads();
    }
    if (i < N) g_rowptr[i] = sh[t] - v;     // local exclusive
    if (t == 1023) g_bsum[blockIdx.x] = sh[1023];
}
__global__ void k_scan2(int nb) {
    __shared__ int sh[64];
    const int t = threadIdx.x;
    int v = (t < nb) ? g_bsum[t] : 0;
    sh[t] = v;
    __syncthreads();
    for (int o = 1; o < 64; o <<= 1) {
        int u = (t >= o) ? sh[t - o] : 0;
        __syncthreads();
        sh[t] += u;
        __syncthreads();
    }
    if (t < nb) g_boff[t] = sh[t] - v;      // exclusive
}
__global__ void k_scan3(int N, int E) {
    const int i = blockIdx.x * 1024 + threadIdx.x;
    if (i < N) {
        int r = g_rowptr[i] + g_boff[i >> 10];
        g_rowptr[i] = r;
        g_cursor[i] = r;
    }
    if (i == 0) g_rowptr[N] = E;
}

// per-edge: place {src, ew} into CSR slot of its target; 4 edges/thread
__global__ void k_place(const int* __restrict__ ei32,
                        const float* __restrict__ ew, int E, int N) {
    int base = (blockIdx.x * blockDim.x + threadIdx.x) * 4;
#pragma unroll
    for (int j = 0; j < 4; j++) {
        int e = base + j;
        if (e >= E) break;
        int r = load_idx(ei32, e, N);
        int c = load_idx(ei32, E + e, N);
        float w = ew[e];
        int pos = atomicAdd(&g_cursor[c], 1);
        if (pos >= 0 && pos < EMAX) {
            g_emeta[pos] = make_int2(r, __float_as_int(w));
        }
    }
}

// per-node: weighted degree (self-loop 1 + segment ew sum) -> dinv
__global__ void k_deg(int N) {
    int i = blockIdx.x * blockDim.x + threadIdx.x;
    if (i >= N) return;
    int s = g_rowptr[i], e = g_rowptr[i + 1];
    float d = 1.0f;
    for (int p = s; p < e; p++) d += __int_as_float(g_emeta[p].y);
    g_dinv[i] = rsqrtf(d);
}

// ----------------------------------------------------------------
// Packed-f32x2 SGEMM, fp16 output: C[M,BN_] = A[M,K] @ B[K,BN_].
// BM=128, BK=16, 256 threads; TN=8 cols/thread; TM_ rows/thread.
template <int BN_, int TM_>
__global__ __launch_bounds__(256)
void k_sgemm2(int layer, const float* __restrict__ Ain, const float* __restrict__ B,
              int M, int K) {
    constexpr int BM = 128, BK = 16, TN = 8;
    constexpr int NCOL = BN_ / TN;            // threads along N
    const float* A = (layer == 0) ? Ain : g_h;
    __half*      C = (layer == 0) ? g_xwh : g_hwh;

    __shared__ float As[BK][BM];              // k-major
    __shared__ float Bs[BK][BN_];

    const int tid = threadIdx.x;
    const int bm  = blockIdx.x * BM;
    const int tx  = tid % NCOL;
    const int ty  = tid / NCOL;

    unsigned long long acc[TM_][TN / 2];
#pragma unroll
    for (int i = 0; i < TM_; i++)
#pragma unroll
        for (int j = 0; j < TN / 2; j++) acc[i][j] = 0ull;

    for (int k0 = 0; k0 < K; k0 += BK) {
        // A tile 128x16 -> transposed into As[k][m]
        {
            int m  = tid >> 1;
            int kc = (tid & 1) * 8;
            int gm = bm + m;
            float4 v0 = make_float4(0.f, 0.f, 0.f, 0.f);
            float4 v1 = v0;
            if (gm < M) {
                const float* p = A + (size_t)gm * K + k0 + kc;
                v0 = *(const float4*)(p);
                v1 = *(const float4*)(p + 4);
            }
            As[kc + 0][m] = v0.x; As[kc + 1][m] = v0.y;
            As[kc + 2][m] = v0.z; As[kc + 3][m] = v0.w;
            As[kc + 4][m] = v1.x; As[kc + 5][m] = v1.y;
            As[kc + 6][m] = v1.z; As[kc + 7][m] = v1.w;
        }
        // B tile 16xBN_
        {
            constexpr int NF4 = BK * BN_ / 4;
#pragma unroll
            for (int i = 0; i < NF4 / 256; i++) {
                int idx4 = i * 256 + tid;
                int r  = idx4 / (BN_ / 4);
                int c4 = idx4 % (BN_ / 4);
                *(float4*)&Bs[r][c4 * 4] =
                    *(const float4*)&B[(size_t)(k0 + r) * BN_ + c4 * 4];
            }
        }
        __syncthreads();

#pragma unroll
        for (int kk = 0; kk < BK; kk++) {
            float av[TM_];
            {
                const float4* ap = (const float4*)&As[kk][ty * TM_];
                float4 a0 = ap[0];
                av[0] = a0.x; av[1] = a0.y; av[2] = a0.z; av[3] = a0.w;
                if constexpr (TM_ == 8) {
                    float4 a1 = ap[1];
                    av[4] = a1.x; av[5] = a1.y; av[6] = a1.z; av[7] = a1.w;
                }
            }
            unsigned long long b2[TN / 2];
            {
                const unsigned long long* bp =
                    (const unsigned long long*)&Bs[kk][tx * TN];
#pragma unroll
                for (int j = 0; j < TN / 2; j++) b2[j] = bp[j];
            }
#pragma unroll
            for (int i = 0; i < TM_; i++) {
                unsigned long long a2 = pack2(av[i]);
#pragma unroll
                for (int j = 0; j < TN / 2; j++) fma2(acc[i][j], a2, b2[j]);
            }
        }
        __syncthreads();
    }

#pragma unroll
    for (int i = 0; i < TM_; i++) {
        int m = bm + ty * TM_ + i;
        if (m < M) {
            __half2 hv[TN / 2];
#pragma unroll
            for (int j = 0; j < TN / 2; j++) {
                float2 f = unpack2(acc[i][j]);
                hv[j] = __floats2half2_rn(f.x, f.y);
            }
            // TN=8 halves = 16B, single uint4 store
            *(uint4*)&C[(size_t)m * BN_ + tx * TN] = *(uint4*)hv;
        }
    }
}

// ----------------------------------------------------------------
// One warp per destination node: self-loop + CSR gather (fp16 src, fp32 acc)
// + bias + ReLU.  out = dc*[dc*x_c + sum_e ew_e*dinv[s_e]*x_{s_e}] + b, ReLU.
template <int F>
__global__ __launch_bounds__(256)
void k_agg(int layer, const float* __restrict__ bias,
           float* __restrict__ outbuf, int N) {
    const __half* src = (layer == 0) ? g_xwh : g_hwh;
    float*        dst = (layer == 0) ? g_h  : outbuf;

    const int gw   = (blockIdx.x * blockDim.x + threadIdx.x) >> 5;
    const int lane = threadIdx.x & 31;
    if (gw >= N) return;

    const int start = g_rowptr[gw];
    const int end   = g_rowptr[gw + 1];
    const float dc  = g_dinv[gw];

    if constexpr (F == 128) {
        // lane owns 4 cols: one uint2 (2x half2) per row
        float4 acc;
        {
            uint2 raw = ((const uint2*)(src + (size_t)gw * F))[lane];
            float2 a = __half22float2(*(__half2*)&raw.x);
            float2 b = __half22float2(*(__half2*)&raw.y);
            acc = make_float4(dc * a.x, dc * a.y, dc * b.x, dc * b.y);
        }
        int e = start;
        for (; e + 4 <= end; e += 4) {
            int2 m0 = g_emeta[e],     m1 = g_emeta[e + 1];
            int2 m2 = g_emeta[e + 2], m3 = g_emeta[e + 3];
            float w0 = __int_as_float(m0.y) * g_dinv[m0.x];
            float w1 = __int_as_float(m1.y) * g_dinv[m1.x];
            float w2 = __int_as_float(m2.y) * g_dinv[m2.x];
            float w3 = __int_as_float(m3.y) * g_dinv[m3.x];
            uint2 r0 = ((const uint2*)(src + (size_t)m0.x * F))[lane];
            uint2 r1 = ((const uint2*)(src + (size_t)m1.x * F))[lane];
            uint2 r2 = ((const uint2*)(src + (size_t)m2.x * F))[lane];
            uint2 r3 = ((const uint2*)(src + (size_t)m3.x * F))[lane];
            float2 a0 = __half22float2(*(__half2*)&r0.x), b0 = __half22float2(*(__half2*)&r0.y);
            float2 a1 = __half22float2(*(__half2*)&r1.x), b1 = __half22float2(*(__half2*)&r1.y);
            float2 a2 = __half22float2(*(__half2*)&r2.x), b2 = __half22float2(*(__half2*)&r2.y);
            float2 a3 = __half22float2(*(__half2*)&r3.x), b3 = __half22float2(*(__half2*)&r3.y);
            acc.x += w0 * a0.x + w1 * a1.x + w2 * a2.x + w3 * a3.x;
            acc.y += w0 * a0.y + w1 * a1.y + w2 * a2.y + w3 * a3.y;
            acc.z += w0 * b0.x + w1 * b1.x + w2 * b2.x + w3 * b3.x;
            acc.w += w0 * b0.y + w1 * b1.y + w2 * b2.y + w3 * b3.y;
        }
        for (; e < end; e++) {
            int2 m = g_emeta[e];
            float w = __int_as_float(m.y) * g_dinv[m.x];
            uint2 r = ((const uint2*)(src + (size_t)m.x * F))[lane];
            float2 a = __half22float2(*(__half2*)&r.x);
            float2 b = __half22float2(*(__half2*)&r.y);
            acc.x += w * a.x; acc.y += w * a.y;
            acc.z += w * b.x; acc.w += w * b.y;
        }
        float4 bv = ((const float4*)bias)[lane];
        acc.x = fmaxf(dc * acc.x + bv.x, 0.f);
        acc.y = fmaxf(dc * acc.y + bv.y, 0.f);
        acc.z = fmaxf(dc * acc.z + bv.z, 0.f);
        acc.w = fmaxf(dc * acc.w + bv.w, 0.f);
        ((float4*)(dst + (size_t)gw * F))[lane] = acc;
    } else {
        // F=64: lane owns 2 cols: one half2 per row
        float2 acc;
        {
            unsigned raw = ((const unsigned*)(src + (size_t)gw * F))[lane];
            float2 a = __half22float2(*(__half2*)&raw);
            acc = make_float2(dc * a.x, dc * a.y);
        }
        int e = start;
        for (; e + 4 <= end; e += 4) {
            int2 m0 = g_emeta[e],     m1 = g_emeta[e + 1];
            int2 m2 = g_emeta[e + 2], m3 = g_emeta[e + 3];
            float w0 = __int_as_float(m0.y) * g_dinv[m0.x];
            float w1 = __int_as_float(m1.y) * g_dinv[m1.x];
            float w2 = __int_as_float(m2.y) * g_dinv[m2.x];
            float w3 = __int_as_float(m3.y) * g_dinv[m3.x];
            unsigned r0 = ((const unsigned*)(src + (size_t)m0.x * F))[lane];
            unsigned r1 = ((const unsigned*)(src + (size_t)m1.x * F))[lane];
            unsigned r2 = ((const unsigned*)(src + (size_t)m2.x * F))[lane];
            unsigned r3 = ((const unsigned*)(src + (size_t)m3.x * F))[lane];
            float2 a0 = __half22float2(*(__half2*)&r0);
            float2 a1 = __half22float2(*(__half2*)&r1);
            float2 a2 = __half22float2(*(__half2*)&r2);
            float2 a3 = __half22float2(*(__half2*)&r3);
            acc.x += w0 * a0.x + w1 * a1.x + w2 * a2.x + w3 * a3.x;
            acc.y += w0 * a0.y + w1 * a1.y + w2 * a2.y + w3 * a3.y;
        }
        for (; e < end; e++) {
            int2 m = g_emeta[e];
            float w = __int_as_float(m.y) * g_dinv[m.x];
            unsigned r = ((const unsigned*)(src + (size_t)m.x * F))[lane];
            float2 a = __half22float2(*(__half2*)&r);
            acc.x += w * a.x; acc.y += w * a.y;
        }
        float2 bv = ((const float2*)bias)[lane];
        acc.x = fmaxf(dc * acc.x + bv.x, 0.f);
        acc.y = fmaxf(dc * acc.y + bv.y, 0.f);
        ((float2*)(dst + (size_t)gw * F))[lane] = acc;
    }
}

// ----------------------------------------------------------------
extern "C" void kernel_launch(void* const* d_in, const int* in_sizes, int n_in,
                              void* d_out, int out_size) {
    const float* x    = (const float*)d_in[0];
    const int*   ei32 = (const int*)d_in[1];     // raw words; dtype probed on device
    const float* ew   = (const float*)d_in[2];
    const float* W0   = (const float*)d_in[3];
    const float* b0   = (const float*)d_in[4];
    const float* W1   = (const float*)d_in[5];
    const float* b1   = (const float*)d_in[6];
    float* out = (float*)d_out;

    const int Fh  = in_sizes[4];            // 128
    const int Fo  = in_sizes[6];            // 64
    const int Fin = in_sizes[3] / Fh;       // 128
    const int N   = in_sizes[0] / Fin;      // 50000
    const int E   = in_sizes[2];            // 800000

    const int TB = 256;
    const int nScanBlocks = (N + 1023) / 1024;

    // dtype probe + CSR prep
    k_reset_flag<<<1, 1>>>();
    k_detect<<<(65536 + TB - 1) / TB, TB>>>(ei32, E);
    k_init<<<(N + TB - 1) / TB, TB>>>(N);
    k_count<<<(E / 4 + TB - 1) / TB + 1, TB>>>(ei32, E, N);
    k_scan1<<<nScanBlocks, 1024>>>(N);
    k_scan2<<<1, 64>>>(nScanBlocks);
    k_scan3<<<nScanBlocks, 1024>>>(N, E);
    k_place<<<(E / 4 + TB - 1) / TB + 1, TB>>>(ei32, ew, E, N);
    k_deg<<<(N + TB - 1) / TB, TB>>>(N);

    // layer 1: g_xwh = fp16(x @ W0) ; g_h = agg(g_xwh) + b0, ReLU  (fp32)
    k_sgemm2<128, 8><<<(N + 127) / 128, 256>>>(0, x, W0, N, Fin);
    k_agg<128><<<(N * 32 + TB - 1) / TB, TB>>>(0, b0, out, N);

    // layer 2: g_hwh = fp16(g_h @ W1) ; out = agg(g_hwh) + b1, ReLU
    k_sgemm2<64, 4><<<(N + 127) / 128, 256>>>(1, nullptr, W1, N, Fh);
    k_agg<64><<<(N * 32 + TB - 1) / TB, TB>>>(1, b1, out, N);
}

// round 11
// speedup vs baseline: 2.3963x; 1.4952x over previous
#include <cuda_runtime.h>
#include <cuda_fp16.h>
#include <stdint.h>

// Problem shape (fixed by dataset): N=50000, E=800000, Fin=Fhid=128, Fout=64
#define NMAX 50176
#define EMAX 800000

// -------- static device scratch (no allocations; referenced directly) ------
__device__ int    g_hi_nonzero;               // dtype probe result
__device__ float  g_dinv[NMAX];
__device__ int    g_cnt[NMAX];
__device__ int    g_rowptr[NMAX + 1];
__device__ int    g_cursor[NMAX];
__device__ int    g_bsum[64];
__device__ int    g_boff[64];
__device__ int2   g_emeta[EMAX];              // {src, ew-as-int-bits}
__device__ __half g_xwh[(size_t)NMAX * 128];  // fp16(x @ W0)   gather source
__device__ float  g_h[(size_t)NMAX * 128];    // layer-1 activations (fp32)
__device__ __half g_hwh[(size_t)NMAX * 64];   // fp16(h @ W1)   gather source

// ----------------------------------------------------------------
__global__ void k_reset_flag() { g_hi_nonzero = 0; }

// Probe edge_index dtype (int64 vs int32) + zero g_cnt in one pass.
// As int32 words, int64 data has all odd words == 0 (high halves).
__global__ void k_detect_init(const int* __restrict__ ei32, int E, int N) {
    int i = blockIdx.x * blockDim.x + threadIdx.x;
    int samples = E < 65536 ? E : 65536;
    if (i < samples) {
        if (ei32[2 * i + 1] != 0) atomicOr(&g_hi_nonzero, 1);
    }
    if (i < N) g_cnt[i] = 0;
}

__device__ __forceinline__ int load_idx(const int* ei32, int pos, int N) {
    int v = (g_hi_nonzero == 0) ? ei32[2 * pos] : ei32[pos];
    v = v < 0 ? 0 : v;
    return v >= N ? N - 1 : v;
}

// per-edge: in-degree histogram
__global__ void k_count(const int* __restrict__ ei32, int E, int N) {
    int e = blockIdx.x * blockDim.x + threadIdx.x;
    if (e >= E) return;
    int c = load_idx(ei32, E + e, N);
    atomicAdd(&g_cnt[c], 1);
}

// ---- parallel 3-stage exclusive scan of g_cnt -> g_rowptr / g_cursor ----
__global__ void k_scan1(int N) {
    __shared__ int sh[1024];
    const int t = threadIdx.x;
    const int i = blockIdx.x * 1024 + t;
    int v = (i < N) ? g_cnt[i] : 0;
    sh[t] = v;
    __syncthreads();
    for (int o = 1; o < 1024; o <<= 1) {
        int u = (t >= o) ? sh[t - o] : 0;
        __syncthreads();
        sh[t] += u;
        __syncthreads();
    }
    if (i < N) g_rowptr[i] = sh[t] - v;     // local exclusive
    if (t == 1023) g_bsum[blockIdx.x] = sh[1023];
}
__global__ void k_scan2(int nb) {
    __shared__ int sh[64];
    const int t = threadIdx.x;
    int v = (t < nb) ? g_bsum[t] : 0;
    sh[t] = v;
    __syncthreads();
    for (int o = 1; o < 64; o <<= 1) {
        int u = (t >= o) ? sh[t - o] : 0;
        __syncthreads();
        sh[t] += u;
        __syncthreads();
    }
    if (t < nb) g_boff[t] = sh[t] - v;      // exclusive
}
__global__ void k_scan3(int N, int E) {
    const int i = blockIdx.x * 1024 + threadIdx.x;
    if (i < N) {
        int r = g_rowptr[i] + g_boff[i >> 10];
        g_rowptr[i] = r;
        g_cursor[i] = r;
    }
    if (i == 0) g_rowptr[N] = E;
}

// per-edge: place {src, ew} into CSR slot of its target
__global__ void k_place(const int* __restrict__ ei32,
                        const float* __restrict__ ew, int E, int N) {
    int e = blockIdx.x * blockDim.x + threadIdx.x;
    if (e >= E) return;
    int r = load_idx(ei32, e, N);
    int c = load_idx(ei32, E + e, N);
    int pos = atomicAdd(&g_cursor[c], 1);
    if (pos >= 0 && pos < EMAX) {
        g_emeta[pos] = make_int2(r, __float_as_int(ew[e]));
    }
}

// per-node: weighted degree (self-loop 1 + segment ew sum) -> dinv
__global__ void k_deg(int N) {
    int i = blockIdx.x * blockDim.x + threadIdx.x;
    if (i >= N) return;
    int s = g_rowptr[i], e = g_rowptr[i + 1];
    float d = 1.0f;
    for (int p = s; p < e; p++) d += __int_as_float(g_emeta[p].y);
    g_dinv[i] = rsqrtf(d);
}

// ----------------------------------------------------------------
// HMMA GEMM: C_fp16[M,BN_] = A_fp32[M,K] @ B_fp32[K,BN_], fp32 accumulate.
// BM=128, K chunked by 64 (fp32->fp16 convert during smem stage).
// 256 threads = 8 warps as 2(m) x 4(n); warp tile 64 x (BN_/4).
// mma.sync.aligned.m16n8k16.row.col.f32.f16.f16.f32 via ldmatrix.
template <int BN_>
__global__ __launch_bounds__(256)
void k_hgemm(int layer, const float* __restrict__ Ain,
             const float* __restrict__ B, int M, int K) {
    constexpr int BM = 128, BKC = 64;
    constexpr int SA = BKC + 8;               // As stride (halves): 72
    constexpr int SB = BN_ + 8;               // Bs stride (halves)
    constexpr int WN = BN_ / 4;               // warp n extent: 32 or 16
    constexpr int NF = WN / 8;                // n-frags per warp: 4 or 2

    const float* A = (layer == 0) ? Ain : g_h;
    __half*      C = (layer == 0) ? g_xwh : g_hwh;

    __shared__ __half As[BM * SA];
    __shared__ __half Bs[BKC * SB];

    const int tid  = threadIdx.x;
    const int wid  = tid >> 5;
    const int lane = tid & 31;
    const int bm   = blockIdx.x * BM;
    const int warp_m = (wid >> 2) * 64;       // 0 or 64
    const int warp_n = (wid & 3) * WN;

    float acc[4][NF][4];
#pragma unroll
    for (int i = 0; i < 4; i++)
#pragma unroll
        for (int j = 0; j < NF; j++)
#pragma unroll
            for (int r = 0; r < 4; r++) acc[i][j][r] = 0.0f;

    for (int c0 = 0; c0 < K; c0 += BKC) {
        // stage A chunk: BM x BKC fp32 -> fp16 smem
        {
            constexpr int NF4 = BM * BKC / 4;     // 2048 float4s
#pragma unroll
            for (int p = 0; p < NF4 / 256; p++) {
                int idx = p * 256 + tid;
                int row = idx / (BKC / 4);
                int k4  = idx % (BKC / 4);
                int gm  = bm + row;
                float4 v = make_float4(0.f, 0.f, 0.f, 0.f);
                if (gm < M) v = *(const float4*)&A[(size_t)gm * K + c0 + k4 * 4];
                __half2 h01 = __floats2half2_rn(v.x, v.y);
                __half2 h23 = __floats2half2_rn(v.z, v.w);
                __half2* dst = (__half2*)&As[row * SA + k4 * 4];
                dst[0] = h01; dst[1] = h23;
            }
        }
        // stage B chunk: BKC x BN_ fp32 -> fp16 smem
        {
            constexpr int NF4 = BKC * BN_ / 4;
#pragma unroll
            for (int p = 0; p < NF4 / 256; p++) {
                int idx = p * 256 + tid;
                int row = idx / (BN_ / 4);
                int c4  = idx % (BN_ / 4);
                float4 v = *(const float4*)&B[(size_t)(c0 + row) * BN_ + c4 * 4];
                __half2 h01 = __floats2half2_rn(v.x, v.y);
                __half2 h23 = __floats2half2_rn(v.z, v.w);
                __half2* dst = (__half2*)&Bs[row * SB + c4 * 4];
                dst[0] = h01; dst[1] = h23;
            }
        }
        __syncthreads();

#pragma unroll
        for (int ks = 0; ks < BKC / 16; ks++) {
            const int kb = ks * 16;
            // A fragments: 4 m-frags of 16x16
            uint32_t a[4][4];
#pragma unroll
            for (int mf = 0; mf < 4; mf++) {
                uint32_t addr = (uint32_t)__cvta_generic_to_shared(
                    &As[(warp_m + mf * 16 + (lane & 15)) * SA + kb + (lane >> 4) * 8]);
                asm volatile(
                    "ldmatrix.sync.aligned.m8n8.x4.shared.b16 {%0,%1,%2,%3}, [%4];"
                    : "=r"(a[mf][0]), "=r"(a[mf][1]), "=r"(a[mf][2]), "=r"(a[mf][3])
                    : "r"(addr));
            }
            // B fragments: NF n-frags of 16x8 (2 per ldmatrix.x4.trans)
            uint32_t b[NF][2];
#pragma unroll
            for (int nq = 0; nq < NF / 2; nq++) {
                uint32_t addr = (uint32_t)__cvta_generic_to_shared(
                    &Bs[(kb + (lane & 15)) * SB + warp_n + nq * 16 + (lane >> 4) * 8]);
                asm volatile(
                    "ldmatrix.sync.aligned.m8n8.x4.trans.shared.b16 {%0,%1,%2,%3}, [%4];"
                    : "=r"(b[2 * nq][0]), "=r"(b[2 * nq][1]),
                      "=r"(b[2 * nq + 1][0]), "=r"(b[2 * nq + 1][1])
                    : "r"(addr));
            }
            // MMA
#pragma unroll
            for (int mf = 0; mf < 4; mf++)
#pragma unroll
                for (int nf = 0; nf < NF; nf++) {
                    asm volatile(
                        "mma.sync.aligned.m16n8k16.row.col.f32.f16.f16.f32 "
                        "{%0,%1,%2,%3}, {%4,%5,%6,%7}, {%8,%9}, {%0,%1,%2,%3};"
                        : "+f"(acc[mf][nf][0]), "+f"(acc[mf][nf][1]),
                          "+f"(acc[mf][nf][2]), "+f"(acc[mf][nf][3])
                        : "r"(a[mf][0]), "r"(a[mf][1]), "r"(a[mf][2]), "r"(a[mf][3]),
                          "r"(b[nf][0]), "r"(b[nf][1]));
                }
        }
        __syncthreads();
    }

    // store: fp16, half2 per fragment row
#pragma unroll
    for (int mf = 0; mf < 4; mf++) {
#pragma unroll
        for (int nf = 0; nf < NF; nf++) {
            int col  = warp_n + nf * 8 + 2 * (lane & 3);
            int row0 = bm + warp_m + mf * 16 + (lane >> 2);
            int row1 = row0 + 8;
            if (row0 < M) {
                __half2 h = __floats2half2_rn(acc[mf][nf][0], acc[mf][nf][1]);
                *(__half2*)&C[(size_t)row0 * BN_ + col] = h;
            }
            if (row1 < M) {
                __half2 h = __floats2half2_rn(acc[mf][nf][2], acc[mf][nf][3]);
                *(__half2*)&C[(size_t)row1 * BN_ + col] = h;
            }
        }
    }
}

// ----------------------------------------------------------------
// One warp per destination node: self-loop + CSR gather (fp16 src, fp32 acc)
// + bias + ReLU.  out = dc*[dc*x_c + sum_e ew_e*dinv[s_e]*x_{s_e}] + b, ReLU.
template <int F>
__global__ __launch_bounds__(256)
void k_agg(int layer, const float* __restrict__ bias,
           float* __restrict__ outbuf, int N) {
    const __half* src = (layer == 0) ? g_xwh : g_hwh;
    float*        dst = (layer == 0) ? g_h  : outbuf;

    const int gw   = (blockIdx.x * blockDim.x + threadIdx.x) >> 5;
    const int lane = threadIdx.x & 31;
    if (gw >= N) return;

    const int start = g_rowptr[gw];
    const int end   = g_rowptr[gw + 1];
    const float dc  = g_dinv[gw];

    if constexpr (F == 128) {
        float4 acc;
        {
            uint2 raw = ((const uint2*)(src + (size_t)gw * F))[lane];
            float2 a = __half22float2(*(__half2*)&raw.x);
            float2 b = __half22float2(*(__half2*)&raw.y);
            acc = make_float4(dc * a.x, dc * a.y, dc * b.x, dc * b.y);
        }
        int e = start;
        for (; e + 4 <= end; e += 4) {
            int2 m0 = g_emeta[e],     m1 = g_emeta[e + 1];
            int2 m2 = g_emeta[e + 2], m3 = g_emeta[e + 3];
            float w0 = __int_as_float(m0.y) * g_dinv[m0.x];
            float w1 = __int_as_float(m1.y) * g_dinv[m1.x];
            float w2 = __int_as_float(m2.y) * g_dinv[m2.x];
            float w3 = __int_as_float(m3.y) * g_dinv[m3.x];
            uint2 r0 = ((const uint2*)(src + (size_t)m0.x * F))[lane];
            uint2 r1 = ((const uint2*)(src + (size_t)m1.x * F))[lane];
            uint2 r2 = ((const uint2*)(src + (size_t)m2.x * F))[lane];
            uint2 r3 = ((const uint2*)(src + (size_t)m3.x * F))[lane];
            float2 a0 = __half22float2(*(__half2*)&r0.x), b0 = __half22float2(*(__half2*)&r0.y);
            float2 a1 = __half22float2(*(__half2*)&r1.x), b1 = __half22float2(*(__half2*)&r1.y);
            float2 a2 = __half22float2(*(__half2*)&r2.x), b2 = __half22float2(*(__half2*)&r2.y);
            float2 a3 = __half22float2(*(__half2*)&r3.x), b3 = __half22float2(*(__half2*)&r3.y);
            acc.x += w0 * a0.x + w1 * a1.x + w2 * a2.x + w3 * a3.x;
            acc.y += w0 * a0.y + w1 * a1.y + w2 * a2.y + w3 * a3.y;
            acc.z += w0 * b0.x + w1 * b1.x + w2 * b2.x + w3 * b3.x;
            acc.w += w0 * b0.y + w1 * b1.y + w2 * b2.y + w3 * b3.y;
        }
        for (; e < end; e++) {
            int2 m = g_emeta[e];
            float w = __int_as_float(m.y) * g_dinv[m.x];
            uint2 r = ((const uint2*)(src + (size_t)m.x * F))[lane];
            float2 a = __half22float2(*(__half2*)&r.x);
            float2 b = __half22float2(*(__half2*)&r.y);
            acc.x += w * a.x; acc.y += w * a.y;
            acc.z += w * b.x; acc.w += w * b.y;
        }
        float4 bv = ((const float4*)bias)[lane];
        acc.x = fmaxf(dc * acc.x + bv.x, 0.f);
        acc.y = fmaxf(dc * acc.y + bv.y, 0.f);
        acc.z = fmaxf(dc * acc.z + bv.z, 0.f);
        acc.w = fmaxf(dc * acc.w + bv.w, 0.f);
        ((float4*)(dst + (size_t)gw * F))[lane] = acc;
    } else {
        float2 acc;
        {
            unsigned raw = ((const unsigned*)(src + (size_t)gw * F))[lane];
            float2 a = __half22float2(*(__half2*)&raw);
            acc = make_float2(dc * a.x, dc * a.y);
        }
        int e = start;
        for (; e + 4 <= end; e += 4) {
            int2 m0 = g_emeta[e],     m1 = g_emeta[e + 1];
            int2 m2 = g_emeta[e + 2], m3 = g_emeta[e + 3];
            float w0 = __int_as_float(m0.y) * g_dinv[m0.x];
            float w1 = __int_as_float(m1.y) * g_dinv[m1.x];
            float w2 = __int_as_float(m2.y) * g_dinv[m2.x];
            float w3 = __int_as_float(m3.y) * g_dinv[m3.x];
            unsigned r0 = ((const unsigned*)(src + (size_t)m0.x * F))[lane];
            unsigned r1 = ((const unsigned*)(src + (size_t)m1.x * F))[lane];
            unsigned r2 = ((const unsigned*)(src + (size_t)m2.x * F))[lane];
            unsigned r3 = ((const unsigned*)(src + (size_t)m3.x * F))[lane];
            float2 a0 = __half22float2(*(__half2*)&r0);
            float2 a1 = __half22float2(*(__half2*)&r1);
            float2 a2 = __half22float2(*(__half2*)&r2);
            float2 a3 = __half22float2(*(__half2*)&r3);
            acc.x += w0 * a0.x + w1 * a1.x + w2 * a2.x + w3 * a3.x;
            acc.y += w0 * a0.y + w1 * a1.y + w2 * a2.y + w3 * a3.y;
        }
        for (; e < end; e++) {
            int2 m = g_emeta[e];
            float w = __int_as_float(m.y) * g_dinv[m.x];
            unsigned r = ((const unsigned*)(src + (size_t)m.x * F))[lane];
            float2 a = __half22float2(*(__half2*)&r);
            acc.x += w * a.x; acc.y += w * a.y;
        }
        float2 bv = ((const float2*)bias)[lane];
        acc.x = fmaxf(dc * acc.x + bv.x, 0.f);
        acc.y = fmaxf(dc * acc.y + bv.y, 0.f);
        ((float2*)(dst + (size_t)gw * F))[lane] = acc;
    }
}

// ----------------------------------------------------------------
extern "C" void kernel_launch(void* const* d_in, const int* in_sizes, int n_in,
                              void* d_out, int out_size) {
    const float* x    = (const float*)d_in[0];
    const int*   ei32 = (const int*)d_in[1];     // raw words; dtype probed on device
    const float* ew   = (const float*)d_in[2];
    const float* W0   = (const float*)d_in[3];
    const float* b0   = (const float*)d_in[4];
    const float* W1   = (const float*)d_in[5];
    const float* b1   = (const float*)d_in[6];
    float* out = (float*)d_out;

    const int Fh  = in_sizes[4];            // 128
    const int Fo  = in_sizes[6];            // 64
    const int Fin = in_sizes[3] / Fh;       // 128
    const int N   = in_sizes[0] / Fin;      // 50000
    const int E   = in_sizes[2];            // 800000

    const int TB = 256;
    const int nScanBlocks = (N + 1023) / 1024;
    const int diGrid = ((N > 65536 ? N : 65536) + TB - 1) / TB;

    // dtype probe + CSR prep
    k_reset_flag<<<1, 1>>>();
    k_detect_init<<<diGrid, TB>>>(ei32, E, N);
    k_count<<<(E + TB - 1) / TB, TB>>>(ei32, E, N);
    k_scan1<<<nScanBlocks, 1024>>>(N);
    k_scan2<<<1, 64>>>(nScanBlocks);
    k_scan3<<<nScanBlocks, 1024>>>(N, E);
    k_place<<<(E + TB - 1) / TB, TB>>>(ei32, ew, E, N);
    k_deg<<<(N + TB - 1) / TB, TB>>>(N);

    // layer 1: g_xwh = fp16(x @ W0) ; g_h = agg(g_xwh) + b0, ReLU  (fp32)
    k_hgemm<128><<<(N + 127) / 128, 256>>>(0, x, W0, N, Fin);
    k_agg<128><<<(N * 32 + TB - 1) / TB, TB>>>(0, b0, out, N);

    // layer 2: g_hwh = fp16(g_h @ W1) ; out = agg(g_hwh) + b1, ReLU
    k_hgemm<64><<<(N + 127) / 128, 256>>>(1, nullptr, W1, N, Fh);
    k_agg<64><<<(N * 32 + TB - 1) / TB, TB>>>(1, b1, out, N);
}

// round 12
// speedup vs baseline: 2.4404x; 1.0184x over previous
#include <cuda_runtime.h>
#include <cuda_fp16.h>
#include <stdint.h>

// Problem shape (fixed by dataset): N=50000, E=800000, Fin=Fhid=128, Fout=64
#define NMAX 50176
#define EMAX 800000

// -------- static device scratch (no allocations; referenced directly) ------
__device__ int    g_hi_nonzero;               // dtype probe (monotone 0->1)
__device__ float  g_dinv[NMAX];
__device__ int    g_cnt[NMAX];
__device__ int    g_rowptr[NMAX + 1];
__device__ int    g_cursor[NMAX];
__device__ int    g_bsum[64];
__device__ int    g_boff[64];
__device__ int2   g_emeta[EMAX];              // {src, ew-as-int-bits}
__device__ __half g_xwh[(size_t)NMAX * 128];  // fp16(x @ W0)   gather source
__device__ float  g_h[(size_t)NMAX * 128];    // layer-1 activations (fp32)
__device__ __half g_hwh[(size_t)NMAX * 64];   // fp16(h @ W1)   gather source

// ----------------------------------------------------------------
// Probe edge_index dtype (int64 vs int32) + zero g_cnt in one pass.
// As int32 words, int64 data has all odd words == 0 (high halves).
// Flag is monotone and its converged value is identical every call,
// so no reset is needed across graph replays.
__global__ void k_detect_init(const int* __restrict__ ei32, int E, int N) {
    int i = blockIdx.x * blockDim.x + threadIdx.x;
    int samples = E < 65536 ? E : 65536;
    if (i < samples) {
        if (ei32[2 * i + 1] != 0) atomicOr(&g_hi_nonzero, 1);
    }
    if (i < N) g_cnt[i] = 0;
}

__device__ __forceinline__ int clampN(int v, int N) {
    v = v < 0 ? 0 : v;
    return v >= N ? N - 1 : v;
}

// per-edge in-degree histogram; 4 edges/thread via int4 index loads
__global__ void k_count(const int* __restrict__ ei32, int E, int N) {
    int base = (blockIdx.x * blockDim.x + threadIdx.x) * 4;
    if (base >= E) return;
    int n = E - base; if (n > 4) n = 4;
    int c[4];
    if (g_hi_nonzero == 0) {                    // int64: col low words
        const int4* p = (const int4*)&ei32[2 * E + 2 * base];
        int4 w0 = p[0], w1 = p[1];
        c[0] = w0.x; c[1] = w0.z; c[2] = w1.x; c[3] = w1.z;
    } else {                                    // int32
        int4 w = *(const int4*)&ei32[E + base];
        c[0] = w.x; c[1] = w.y; c[2] = w.z; c[3] = w.w;
    }
#pragma unroll
    for (int j = 0; j < 4; j++) {
        if (j < n) atomicAdd(&g_cnt[clampN(c[j], N)], 1);
    }
}

// ---- parallel 3-stage exclusive scan of g_cnt -> g_rowptr / g_cursor ----
__global__ void k_scan1(int N) {
    __shared__ int sh[1024];
    const int t = threadIdx.x;
    const int i = blockIdx.x * 1024 + t;
    int v = (i < N) ? g_cnt[i] : 0;
    sh[t] = v;
    __syncthreads();
    for (int o = 1; o < 1024; o <<= 1) {
        int u = (t >= o) ? sh[t - o] : 0;
        __syncthreads();
        sh[t] += u;
        __syncthreads();
    }
    if (i < N) g_rowptr[i] = sh[t] - v;     // local exclusive
    if (t == 1023) g_bsum[blockIdx.x] = sh[1023];
}
__global__ void k_scan2(int nb) {
    __shared__ int sh[64];
    const int t = threadIdx.x;
    int v = (t < nb) ? g_bsum[t] : 0;
    sh[t] = v;
    __syncthreads();
    for (int o = 1; o < 64; o <<= 1) {
        int u = (t >= o) ? sh[t - o] : 0;
        __syncthreads();
        sh[t] += u;
        __syncthreads();
    }
    if (t < nb) g_boff[t] = sh[t] - v;      // exclusive
}
__global__ void k_scan3(int N, int E) {
    const int i = blockIdx.x * 1024 + threadIdx.x;
    if (i < N) {
        int r = g_rowptr[i] + g_boff[i >> 10];
        g_rowptr[i] = r;
        g_cursor[i] = r;
    }
    if (i == 0) g_rowptr[N] = E;
}

// per-edge: place {src, ew} into CSR slot of target; 4 edges/thread, int4 loads
__global__ void k_place(const int* __restrict__ ei32,
                        const float* __restrict__ ew, int E, int N) {
    int base = (blockIdx.x * blockDim.x + threadIdx.x) * 4;
    if (base >= E) return;
    int n = E - base; if (n > 4) n = 4;
    int r[4], c[4];
    if (g_hi_nonzero == 0) {                    // int64 low words
        const int4* pr = (const int4*)&ei32[2 * base];
        int4 a0 = pr[0], a1 = pr[1];
        r[0] = a0.x; r[1] = a0.z; r[2] = a1.x; r[3] = a1.z;
        const int4* pc = (const int4*)&ei32[2 * E + 2 * base];
        int4 b0 = pc[0], b1 = pc[1];
        c[0] = b0.x; c[1] = b0.z; c[2] = b1.x; c[3] = b1.z;
    } else {
        int4 a = *(const int4*)&ei32[base];
        r[0] = a.x; r[1] = a.y; r[2] = a.z; r[3] = a.w;
        int4 b = *(const int4*)&ei32[E + base];
        c[0] = b.x; c[1] = b.y; c[2] = b.z; c[3] = b.w;
    }
    float4 wv = *(const float4*)&ew[base];
    float w[4] = {wv.x, wv.y, wv.z, wv.w};
#pragma unroll
    for (int j = 0; j < 4; j++) {
        if (j < n) {
            int pos = atomicAdd(&g_cursor[clampN(c[j], N)], 1);
            if (pos >= 0 && pos < EMAX)
                g_emeta[pos] = make_int2(clampN(r[j], N), __float_as_int(w[j]));
        }
    }
}

// per-node: weighted degree (self-loop 1 + segment ew sum) -> dinv
__global__ void k_deg(int N) {
    int i = blockIdx.x * blockDim.x + threadIdx.x;
    if (i >= N) return;
    int s = g_rowptr[i], e = g_rowptr[i + 1];
    float d = 1.0f;
    for (int p = s; p < e; p++) d += __int_as_float(g_emeta[p].y);
    g_dinv[i] = rsqrtf(d);
}

// ----------------------------------------------------------------
// HMMA GEMM: C_fp16[M,BN_] = A_fp32[M,K] @ B_fp32[K,BN_], fp32 accumulate.
template <int BN_>
__global__ __launch_bounds__(256)
void k_hgemm(int layer, const float* __restrict__ Ain,
             const float* __restrict__ B, int M, int K) {
    constexpr int BM = 128, BKC = 64;
    constexpr int SA = BKC + 8;
    constexpr int SB = BN_ + 8;
    constexpr int WN = BN_ / 4;
    constexpr int NF = WN / 8;

    const float* A = (layer == 0) ? Ain : g_h;
    __half*      C = (layer == 0) ? g_xwh : g_hwh;

    __shared__ __half As[BM * SA];
    __shared__ __half Bs[BKC * SB];

    const int tid  = threadIdx.x;
    const int wid  = tid >> 5;
    const int lane = tid & 31;
    const int bm   = blockIdx.x * BM;
    const int warp_m = (wid >> 2) * 64;
    const int warp_n = (wid & 3) * WN;

    float acc[4][NF][4];
#pragma unroll
    for (int i = 0; i < 4; i++)
#pragma unroll
        for (int j = 0; j < NF; j++)
#pragma unroll
            for (int r = 0; r < 4; r++) acc[i][j][r] = 0.0f;

    for (int c0 = 0; c0 < K; c0 += BKC) {
        {
            constexpr int NF4 = BM * BKC / 4;
#pragma unroll
            for (int p = 0; p < NF4 / 256; p++) {
                int idx = p * 256 + tid;
                int row = idx / (BKC / 4);
                int k4  = idx % (BKC / 4);
                int gm  = bm + row;
                float4 v = make_float4(0.f, 0.f, 0.f, 0.f);
                if (gm < M) v = *(const float4*)&A[(size_t)gm * K + c0 + k4 * 4];
                __half2 h01 = __floats2half2_rn(v.x, v.y);
                __half2 h23 = __floats2half2_rn(v.z, v.w);
                __half2* dst = (__half2*)&As[row * SA + k4 * 4];
                dst[0] = h01; dst[1] = h23;
            }
        }
        {
            constexpr int NF4 = BKC * BN_ / 4;
#pragma unroll
            for (int p = 0; p < NF4 / 256; p++) {
                int idx = p * 256 + tid;
                int row = idx / (BN_ / 4);
                int c4  = idx % (BN_ / 4);
                float4 v = *(const float4*)&B[(size_t)(c0 + row) * BN_ + c4 * 4];
                __half2 h01 = __floats2half2_rn(v.x, v.y);
                __half2 h23 = __floats2half2_rn(v.z, v.w);
                __half2* dst = (__half2*)&Bs[row * SB + c4 * 4];
                dst[0] = h01; dst[1] = h23;
            }
        }
        __syncthreads();

#pragma unroll
        for (int ks = 0; ks < BKC / 16; ks++) {
            const int kb = ks * 16;
            uint32_t a[4][4];
#pragma unroll
            for (int mf = 0; mf < 4; mf++) {
                uint32_t addr = (uint32_t)__cvta_generic_to_shared(
                    &As[(warp_m + mf * 16 + (lane & 15)) * SA + kb + (lane >> 4) * 8]);
                asm volatile(
                    "ldmatrix.sync.aligned.m8n8.x4.shared.b16 {%0,%1,%2,%3}, [%4];"
                    : "=r"(a[mf][0]), "=r"(a[mf][1]), "=r"(a[mf][2]), "=r"(a[mf][3])
                    : "r"(addr));
            }
            uint32_t b[NF][2];
#pragma unroll
            for (int nq = 0; nq < NF / 2; nq++) {
                uint32_t addr = (uint32_t)__cvta_generic_to_shared(
                    &Bs[(kb + (lane & 15)) * SB + warp_n + nq * 16 + (lane >> 4) * 8]);
                asm volatile(
                    "ldmatrix.sync.aligned.m8n8.x4.trans.shared.b16 {%0,%1,%2,%3}, [%4];"
                    : "=r"(b[2 * nq][0]), "=r"(b[2 * nq][1]),
                      "=r"(b[2 * nq + 1][0]), "=r"(b[2 * nq + 1][1])
                    : "r"(addr));
            }
#pragma unroll
            for (int mf = 0; mf < 4; mf++)
#pragma unroll
                for (int nf = 0; nf < NF; nf++) {
                    asm volatile(
                        "mma.sync.aligned.m16n8k16.row.col.f32.f16.f16.f32 "
                        "{%0,%1,%2,%3}, {%4,%5,%6,%7}, {%8,%9}, {%0,%1,%2,%3};"
                        : "+f"(acc[mf][nf][0]), "+f"(acc[mf][nf][1]),
                          "+f"(acc[mf][nf][2]), "+f"(acc[mf][nf][3])
                        : "r"(a[mf][0]), "r"(a[mf][1]), "r"(a[mf][2]), "r"(a[mf][3]),
                          "r"(b[nf][0]), "r"(b[nf][1]));
                }
        }
        __syncthreads();
    }

#pragma unroll
    for (int mf = 0; mf < 4; mf++) {
#pragma unroll
        for (int nf = 0; nf < NF; nf++) {
            int col  = warp_n + nf * 8 + 2 * (lane & 3);
            int row0 = bm + warp_m + mf * 16 + (lane >> 2);
            int row1 = row0 + 8;
            if (row0 < M) {
                __half2 h = __floats2half2_rn(acc[mf][nf][0], acc[mf][nf][1]);
                *(__half2*)&C[(size_t)row0 * BN_ + col] = h;
            }
            if (row1 < M) {
                __half2 h = __floats2half2_rn(acc[mf][nf][2], acc[mf][nf][3]);
                *(__half2*)&C[(size_t)row1 * BN_ + col] = h;
            }
        }
    }
}

// ----------------------------------------------------------------
// One warp per destination node: self-loop + CSR gather (fp16 src, fp32 acc)
// + bias + ReLU.
template <int F>
__global__ __launch_bounds__(256)
void k_agg(int layer, const float* __restrict__ bias,
           float* __restrict__ outbuf, int N) {
    const __half* src = (layer == 0) ? g_xwh : g_hwh;
    float*        dst = (layer == 0) ? g_h  : outbuf;

    const int gw   = (blockIdx.x * blockDim.x + threadIdx.x) >> 5;
    const int lane = threadIdx.x & 31;
    if (gw >= N) return;

    const int start = g_rowptr[gw];
    const int end   = g_rowptr[gw + 1];
    const float dc  = g_dinv[gw];

    if constexpr (F == 128) {
        float4 acc;
        {
            uint2 raw = ((const uint2*)(src + (size_t)gw * F))[lane];
            float2 a = __half22float2(*(__half2*)&raw.x);
            float2 b = __half22float2(*(__half2*)&raw.y);
            acc = make_float4(dc * a.x, dc * a.y, dc * b.x, dc * b.y);
        }
        int e = start;
        for (; e + 4 <= end; e += 4) {
            int2 m0 = g_emeta[e],     m1 = g_emeta[e + 1];
            int2 m2 = g_emeta[e + 2], m3 = g_emeta[e + 3];
            float w0 = __int_as_float(m0.y) * g_dinv[m0.x];
            float w1 = __int_as_float(m1.y) * g_dinv[m1.x];
            float w2 = __int_as_float(m2.y) * g_dinv[m2.x];
            float w3 = __int_as_float(m3.y) * g_dinv[m3.x];
            uint2 r0 = ((const uint2*)(src + (size_t)m0.x * F))[lane];
            uint2 r1 = ((const uint2*)(src + (size_t)m1.x * F))[lane];
            uint2 r2 = ((const uint2*)(src + (size_t)m2.x * F))[lane];
            uint2 r3 = ((const uint2*)(src + (size_t)m3.x * F))[lane];
            float2 a0 = __half22float2(*(__half2*)&r0.x), b0 = __half22float2(*(__half2*)&r0.y);
            float2 a1 = __half22float2(*(__half2*)&r1.x), b1 = __half22float2(*(__half2*)&r1.y);
            float2 a2 = __half22float2(*(__half2*)&r2.x), b2 = __half22float2(*(__half2*)&r2.y);
            float2 a3 = __half22float2(*(__half2*)&r3.x), b3 = __half22float2(*(__half2*)&r3.y);
            acc.x += w0 * a0.x + w1 * a1.x + w2 * a2.x + w3 * a3.x;
            acc.y += w0 * a0.y + w1 * a1.y + w2 * a2.y + w3 * a3.y;
            acc.z += w0 * b0.x + w1 * b1.x + w2 * b2.x + w3 * b3.x;
            acc.w += w0 * b0.y + w1 * b1.y + w2 * b2.y + w3 * b3.y;
        }
        for (; e < end; e++) {
            int2 m = g_emeta[e];
            float w = __int_as_float(m.y) * g_dinv[m.x];
            uint2 r = ((const uint2*)(src + (size_t)m.x * F))[lane];
            float2 a = __half22float2(*(__half2*)&r.x);
            float2 b = __half22float2(*(__half2*)&r.y);
            acc.x += w * a.x; acc.y += w * a.y;
            acc.z += w * b.x; acc.w += w * b.y;
        }
        float4 bv = ((const float4*)bias)[lane];
        acc.x = fmaxf(dc * acc.x + bv.x, 0.f);
        acc.y = fmaxf(dc * acc.y + bv.y, 0.f);
        acc.z = fmaxf(dc * acc.z + bv.z, 0.f);
        acc.w = fmaxf(dc * acc.w + bv.w, 0.f);
        ((float4*)(dst + (size_t)gw * F))[lane] = acc;
    } else {
        float2 acc;
        {
            unsigned raw = ((const unsigned*)(src + (size_t)gw * F))[lane];
            float2 a = __half22float2(*(__half2*)&raw);
            acc = make_float2(dc * a.x, dc * a.y);
        }
        int e = start;
        for (; e + 4 <= end; e += 4) {
            int2 m0 = g_emeta[e],     m1 = g_emeta[e + 1];
            int2 m2 = g_emeta[e + 2], m3 = g_emeta[e + 3];
            float w0 = __int_as_float(m0.y) * g_dinv[m0.x];
            float w1 = __int_as_float(m1.y) * g_dinv[m1.x];
            float w2 = __int_as_float(m2.y) * g_dinv[m2.x];
            float w3 = __int_as_float(m3.y) * g_dinv[m3.x];
            unsigned r0 = ((const unsigned*)(src + (size_t)m0.x * F))[lane];
            unsigned r1 = ((const unsigned*)(src + (size_t)m1.x * F))[lane];
            unsigned r2 = ((const unsigned*)(src + (size_t)m2.x * F))[lane];
            unsigned r3 = ((const unsigned*)(src + (size_t)m3.x * F))[lane];
            float2 a0 = __half22float2(*(__half2*)&r0);
            float2 a1 = __half22float2(*(__half2*)&r1);
            float2 a2 = __half22float2(*(__half2*)&r2);
            float2 a3 = __half22float2(*(__half2*)&r3);
            acc.x += w0 * a0.x + w1 * a1.x + w2 * a2.x + w3 * a3.x;
            acc.y += w0 * a0.y + w1 * a1.y + w2 * a2.y + w3 * a3.y;
        }
        for (; e < end; e++) {
            int2 m = g_emeta[e];
            float w = __int_as_float(m.y) * g_dinv[m.x];
            unsigned r = ((const unsigned*)(src + (size_t)m.x * F))[lane];
            float2 a = __half22float2(*(__half2*)&r);
            acc.x += w * a.x; acc.y += w * a.y;
        }
        float2 bv = ((const float2*)bias)[lane];
        acc.x = fmaxf(dc * acc.x + bv.x, 0.f);
        acc.y = fmaxf(dc * acc.y + bv.y, 0.f);
        ((float2*)(dst + (size_t)gw * F))[lane] = acc;
    }
}

// ----------------------------------------------------------------
extern "C" void kernel_launch(void* const* d_in, const int* in_sizes, int n_in,
                              void* d_out, int out_size) {
    const float* x    = (const float*)d_in[0];
    const int*   ei32 = (const int*)d_in[1];     // raw words; dtype probed on device
    const float* ew   = (const float*)d_in[2];
    const float* W0   = (const float*)d_in[3];
    const float* b0   = (const float*)d_in[4];
    const float* W1   = (const float*)d_in[5];
    const float* b1   = (const float*)d_in[6];
    float* out = (float*)d_out;

    const int Fh  = in_sizes[4];            // 128
    const int Fo  = in_sizes[6];            // 64
    const int Fin = in_sizes[3] / Fh;       // 128
    const int N   = in_sizes[0] / Fin;      // 50000
    const int E   = in_sizes[2];            // 800000

    // side stream + events, created once on the first (uncaptured) call
    static cudaStream_t s2 = nullptr;
    static cudaEvent_t evFork = nullptr, evJoin = nullptr;
    if (s2 == nullptr) {
        cudaStreamCreateWithFlags(&s2, cudaStreamNonBlocking);
        cudaEventCreateWithFlags(&evFork, cudaEventDisableTiming);
        cudaEventCreateWithFlags(&evJoin, cudaEventDisableTiming);
    }

    const int TB = 256;
    const int nScanBlocks = (N + 1023) / 1024;
    const int diGrid = ((N > 65536 ? N : 65536) + TB - 1) / TB;

    // fork: GEMM-1 (depends only on inputs) runs on s2, overlapping CSR prep
    cudaEventRecord(evFork, 0);
    cudaStreamWaitEvent(s2, evFork, 0);
    k_hgemm<128><<<(N + 127) / 128, 256, 0, s2>>>(0, x, W0, N, Fin);
    cudaEventRecord(evJoin, s2);

    // CSR prep chain on the main stream
    k_detect_init<<<diGrid, TB>>>(ei32, E, N);
    k_count<<<(E / 4 + TB - 1) / TB, TB>>>(ei32, E, N);
    k_scan1<<<nScanBlocks, 1024>>>(N);
    k_scan2<<<1, 64>>>(nScanBlocks);
    k_scan3<<<nScanBlocks, 1024>>>(N, E);
    k_place<<<(E / 4 + TB - 1) / TB, TB>>>(ei32, ew, E, N);
    k_deg<<<(N + TB - 1) / TB, TB>>>(N);

    // join: agg-1 needs both CSR prep and GEMM-1
    cudaStreamWaitEvent(0, evJoin, 0);
    k_agg<128><<<(N * 32 + TB - 1) / TB, TB>>>(0, b0, out, N);

    // layer 2
    k_hgemm<64><<<(N + 127) / 128, 256>>>(1, nullptr, W1, N, Fh);
    k_agg<64><<<(N * 32 + TB - 1) / TB, TB>>>(1, b1, out, N);
}